// round 15
// baseline (speedup 1.0000x reference)
#include <cuda_runtime.h>
#include <math.h>
#include <stdint.h>

// ---------------- scratch (device globals; no allocations) ----------------
#define MAXN 76800
#define MAXE 768000
#define MAXNF (76800u * 216u)
#define MOLN 10240
#define MOLE 40960
#define MOLNF (10240u * 312u)

// protein-branch buffers
__device__ float g_Y[MAXNF];
__device__ float g_A[MAXNF];
__device__ float g_B[MAXNF];
__device__ float g_nrm[MAXN];
__device__ int   g_deg[MAXN];
__device__ int   g_cur[MAXN];
__device__ int   g_rowptr[MAXN + 1];
__device__ int   g_csr[MAXE];
__device__ int   g_bsum[128];
__device__ int   g_gptr[257];
__device__ float g_pool[256 * 312];
__device__ float g_fc1[256 * 1024];
__device__ float g_part[8 * 256 * 1024];
// molecule-branch buffers (private, for stream overlap)
__device__ float m_Y[MOLNF];
__device__ float m_A[MOLNF];
__device__ float m_B[MOLNF];
__device__ float m_nrm[MOLN];
__device__ int   m_deg[MOLN];
__device__ int   m_cur[MOLN];
__device__ int   m_rowptr[MOLN + 1];
__device__ int   m_csr[MOLE];
__device__ int   m_bsum[128];
__device__ int   m_gptr[257];
__device__ float m_pool[256 * 312];
__device__ float m_fc1[256 * 1024];
__device__ float m_part[8 * 256 * 1024];
// shared tail
__device__ float g_cat[256 * 256];
__device__ float g_head[256 * 512];

static inline int gdiv(int n, int d) { return (n + d - 1) / d; }

// ---------------- small utility kernels ----------------
__global__ void k_zeroi(int* a, int n) {
    int i = blockIdx.x * blockDim.x + threadIdx.x;
    if (i < n) a[i] = 0;
}

__global__ void k_hist(const int* __restrict__ idx, int* __restrict__ acc, int n) {
    int i = blockIdx.x * blockDim.x + threadIdx.x;
    if (i < n) atomicAdd(&acc[idx[i]], 1);
}

// ---- multi-block exclusive scan ----
__global__ void k_scan_blk(const int* __restrict__ in, int* __restrict__ out,
                           int* __restrict__ bsum, int n) {
    __shared__ int wsum[32];
    int tid = threadIdx.x;
    int lane = tid & 31, wid = tid >> 5;
    int i = blockIdx.x * 1024 + tid;
    int v = (i < n) ? in[i] : 0;
    int s = v;
#pragma unroll
    for (int off = 1; off < 32; off <<= 1) {
        int t = __shfl_up_sync(0xffffffffu, s, off);
        if (lane >= off) s += t;
    }
    if (lane == 31) wsum[wid] = s;
    __syncthreads();
    if (wid == 0) {
        int ws = wsum[lane];
#pragma unroll
        for (int off = 1; off < 32; off <<= 1) {
            int t = __shfl_up_sync(0xffffffffu, ws, off);
            if (lane >= off) ws += t;
        }
        wsum[lane] = ws;
    }
    __syncthreads();
    int wofs = (wid > 0) ? wsum[wid - 1] : 0;
    int incl = wofs + s;
    if (i < n) out[i] = incl - v;
    if (tid == 1023) bsum[blockIdx.x] = incl;
}

__global__ void k_scan_small(int* __restrict__ b, int nb) {
    __shared__ int wsum[4];
    int tid = threadIdx.x;
    int lane = tid & 31, wid = tid >> 5;
    int v = (tid < nb) ? b[tid] : 0;
    int s = v;
#pragma unroll
    for (int off = 1; off < 32; off <<= 1) {
        int t = __shfl_up_sync(0xffffffffu, s, off);
        if (lane >= off) s += t;
    }
    if (lane == 31) wsum[wid] = s;
    __syncthreads();
    if (tid == 0) {
        int c = 0;
        for (int w = 0; w < 4; w++) { int t = wsum[w]; wsum[w] = c; c += t; }
    }
    __syncthreads();
    int excl = wsum[wid] + s - v;
    __syncthreads();
    if (tid < nb) b[tid] = excl;
    if (tid == nb - 1) b[nb] = excl + v;
}

// phase 3 fused: add block offsets, compute nrm, zero cur
__global__ void k_scan_add(int* __restrict__ out, const int* __restrict__ bsum,
                           const int* __restrict__ deg, float* __restrict__ nrm,
                           int* __restrict__ cur, int n, int nb) {
    int i = blockIdx.x * blockDim.x + threadIdx.x;
    if (i < n) {
        out[i] += bsum[i >> 10];
        nrm[i] = rsqrtf((float)deg[i] + 1.f);
        cur[i] = 0;
    }
    if (i == 0) out[n] = bsum[nb];
}

// fused per-graph histogram + exclusive scan (256 graphs), single block 1024
__global__ void k_ghist(const int* __restrict__ bat, int* __restrict__ gptr, int n) {
    __shared__ int bins[256];
    __shared__ int wsum[8];
    int tid = threadIdx.x;
    int lane = tid & 31, wid = tid >> 5;
    if (tid < 256) bins[tid] = 0;
    __syncthreads();
    for (int i = tid; i < n; i += 1024) atomicAdd(&bins[bat[i]], 1);
    __syncthreads();
    int v = (tid < 256) ? bins[tid] : 0;
    int s = v;
#pragma unroll
    for (int off = 1; off < 32; off <<= 1) {
        int t = __shfl_up_sync(0xffffffffu, s, off);
        if (lane >= off) s += t;
    }
    if (lane == 31 && wid < 8) wsum[wid] = s;
    __syncthreads();
    if (tid == 0) {
        int c = 0;
        for (int w = 0; w < 8; w++) { int t = wsum[w]; wsum[w] = c; c += t; }
    }
    __syncthreads();
    if (tid < 256) {
        int excl = wsum[wid] + s - v;
        gptr[tid] = excl;
        if (tid == 255) gptr[256] = excl + v;
    }
}

__global__ void k_fill(const int* __restrict__ src, const int* __restrict__ dst,
                       const int* __restrict__ rowptr, int* __restrict__ cur,
                       int* __restrict__ csr, int E) {
    int e = blockIdx.x * blockDim.x + threadIdx.x;
    if (e >= E) return;
    int d = dst[e];
    int p = rowptr[d] + atomicAdd(&cur[d], 1);
    csr[p] = src[e];
}

// ---------------- aggregation: y_i = nrm_i*(sum nrm_s x_s + nrm_i x_i) [+bias][relu]
template <int NF>
__global__ void k_agg(const float* __restrict__ x, const float* __restrict__ nrm,
                      const int* __restrict__ rowptr, const int* __restrict__ csr,
                      float* __restrict__ y, int N, int F,
                      const float* __restrict__ bias, int dorelu) {
    int warp = (blockIdx.x * blockDim.x + threadIdx.x) >> 5;
    int lane = threadIdx.x & 31;
    if (warp >= N) return;
    int beg = rowptr[warp], end = rowptr[warp + 1];
    float ni = nrm[warp];

    float acc[NF];
#pragma unroll
    for (int j = 0; j < NF; j++) acc[j] = 0.f;

    int e = beg;
    for (; e + 1 < end; e += 2) {
        int s0 = csr[e], s1 = csr[e + 1];
        float n0 = nrm[s0], n1 = nrm[s1];
        const float* x0 = x + (size_t)s0 * F;
        const float* x1 = x + (size_t)s1 * F;
#pragma unroll
        for (int j = 0; j < NF; j++) {
            int f = lane + 32 * j;
            if (f < F) acc[j] += x0[f] * n0 + x1[f] * n1;
        }
    }
    if (e < end) {
        int s0 = csr[e];
        float n0 = nrm[s0];
        const float* x0 = x + (size_t)s0 * F;
#pragma unroll
        for (int j = 0; j < NF; j++) {
            int f = lane + 32 * j;
            if (f < F) acc[j] += x0[f] * n0;
        }
    }
    const float* xi = x + (size_t)warp * F;
    float* yi = y + (size_t)warp * F;
#pragma unroll
    for (int j = 0; j < NF; j++) {
        int f = lane + 32 * j;
        if (f < F) {
            float v = ni * (acc[j] + ni * xi[f]);
            if (bias) v += bias[f];
            if (dorelu) v = fmaxf(v, 0.f);
            yi[f] = v;
        }
    }
}

// float2 variant (F % 2 == 0); F2 = F/2; 4-edge unroll
template <int NJ>
__global__ void k_agg2(const float2* __restrict__ x, const float* __restrict__ nrm,
                       const int* __restrict__ rowptr, const int* __restrict__ csr,
                       float2* __restrict__ y, int N, int F2,
                       const float2* __restrict__ bias, int dorelu) {
    int warp = (blockIdx.x * blockDim.x + threadIdx.x) >> 5;
    int lane = threadIdx.x & 31;
    if (warp >= N) return;
    int beg = rowptr[warp], end = rowptr[warp + 1];
    float ni = nrm[warp];

    float2 acc[NJ];
#pragma unroll
    for (int j = 0; j < NJ; j++) acc[j] = make_float2(0.f, 0.f);

    int e = beg;
    for (; e + 3 < end; e += 4) {
        int s0 = csr[e], s1 = csr[e + 1], s2 = csr[e + 2], s3 = csr[e + 3];
        float n0 = nrm[s0], n1 = nrm[s1], n2 = nrm[s2], n3 = nrm[s3];
        const float2* x0 = x + (size_t)s0 * F2;
        const float2* x1 = x + (size_t)s1 * F2;
        const float2* x2 = x + (size_t)s2 * F2;
        const float2* x3 = x + (size_t)s3 * F2;
#pragma unroll
        for (int j = 0; j < NJ; j++) {
            int f = lane + 32 * j;
            if (f < F2) {
                float2 v0 = x0[f], v1 = x1[f], v2 = x2[f], v3 = x3[f];
                acc[j].x += v0.x * n0 + v1.x * n1 + v2.x * n2 + v3.x * n3;
                acc[j].y += v0.y * n0 + v1.y * n1 + v2.y * n2 + v3.y * n3;
            }
        }
    }
    for (; e < end; e++) {
        int s0 = csr[e];
        float n0 = nrm[s0];
        const float2* x0 = x + (size_t)s0 * F2;
#pragma unroll
        for (int j = 0; j < NJ; j++) {
            int f = lane + 32 * j;
            if (f < F2) {
                float2 v0 = x0[f];
                acc[j].x += v0.x * n0;
                acc[j].y += v0.y * n0;
            }
        }
    }
    const float2* xi = x + (size_t)warp * F2;
    float2* yi = y + (size_t)warp * F2;
#pragma unroll
    for (int j = 0; j < NJ; j++) {
        int f = lane + 32 * j;
        if (f < F2) {
            float2 v = xi[f];
            float2 o;
            o.x = ni * (acc[j].x + ni * v.x);
            o.y = ni * (acc[j].y + ni * v.y);
            if (bias) { float2 b = bias[f]; o.x += b.x; o.y += b.y; }
            if (dorelu) { o.x = fmaxf(o.x, 0.f); o.y = fmaxf(o.y, 0.f); }
            yi[f] = o;
        }
    }
}

// float4 variant (F % 4 == 0); F4 = F/4; 4-edge unroll
template <int NJ>
__global__ void k_agg4(const float4* __restrict__ x, const float* __restrict__ nrm,
                       const int* __restrict__ rowptr, const int* __restrict__ csr,
                       float4* __restrict__ y, int N, int F4,
                       const float4* __restrict__ bias, int dorelu) {
    int warp = (blockIdx.x * blockDim.x + threadIdx.x) >> 5;
    int lane = threadIdx.x & 31;
    if (warp >= N) return;
    int beg = rowptr[warp], end = rowptr[warp + 1];
    float ni = nrm[warp];

    float4 acc[NJ];
#pragma unroll
    for (int j = 0; j < NJ; j++) acc[j] = make_float4(0.f, 0.f, 0.f, 0.f);

    int e = beg;
    for (; e + 3 < end; e += 4) {
        int s0 = csr[e], s1 = csr[e + 1], s2 = csr[e + 2], s3 = csr[e + 3];
        float n0 = nrm[s0], n1 = nrm[s1], n2 = nrm[s2], n3 = nrm[s3];
        const float4* x0 = x + (size_t)s0 * F4;
        const float4* x1 = x + (size_t)s1 * F4;
        const float4* x2 = x + (size_t)s2 * F4;
        const float4* x3 = x + (size_t)s3 * F4;
#pragma unroll
        for (int j = 0; j < NJ; j++) {
            int f = lane + 32 * j;
            if (f < F4) {
                float4 v0 = x0[f], v1 = x1[f], v2 = x2[f], v3 = x3[f];
                acc[j].x += v0.x * n0 + v1.x * n1 + v2.x * n2 + v3.x * n3;
                acc[j].y += v0.y * n0 + v1.y * n1 + v2.y * n2 + v3.y * n3;
                acc[j].z += v0.z * n0 + v1.z * n1 + v2.z * n2 + v3.z * n3;
                acc[j].w += v0.w * n0 + v1.w * n1 + v2.w * n2 + v3.w * n3;
            }
        }
    }
    for (; e < end; e++) {
        int s0 = csr[e];
        float n0 = nrm[s0];
        const float4* x0 = x + (size_t)s0 * F4;
#pragma unroll
        for (int j = 0; j < NJ; j++) {
            int f = lane + 32 * j;
            if (f < F4) {
                float4 v0 = x0[f];
                acc[j].x += v0.x * n0;
                acc[j].y += v0.y * n0;
                acc[j].z += v0.z * n0;
                acc[j].w += v0.w * n0;
            }
        }
    }
    const float4* xi = x + (size_t)warp * F4;
    float4* yi = y + (size_t)warp * F4;
#pragma unroll
    for (int j = 0; j < NJ; j++) {
        int f = lane + 32 * j;
        if (f < F4) {
            float4 v = xi[f];
            float4 o;
            o.x = ni * (acc[j].x + ni * v.x);
            o.y = ni * (acc[j].y + ni * v.y);
            o.z = ni * (acc[j].z + ni * v.z);
            o.w = ni * (acc[j].w + ni * v.w);
            if (bias) {
                float4 b = bias[f];
                o.x += b.x; o.y += b.y; o.z += b.z; o.w += b.w;
            }
            if (dorelu) {
                o.x = fmaxf(o.x, 0.f); o.y = fmaxf(o.y, 0.f);
                o.z = fmaxf(o.z, 0.f); o.w = fmaxf(o.w, 0.f);
            }
            yi[f] = o;
        }
    }
}

static void launch_agg(const float* x, const float* nrm, const int* rp, const int* csr,
                       float* y, int N, int F, const float* bias, int dorelu,
                       cudaStream_t st) {
    int blocks = gdiv(N, 8);
    if ((F & 3) == 0) {
        int F4 = F >> 2;
        int nj = gdiv(F4, 32);
        if (nj == 1)      k_agg4<1><<<blocks, 256, 0, st>>>((const float4*)x, nrm, rp, csr, (float4*)y, N, F4, (const float4*)bias, dorelu);
        else if (nj == 2) k_agg4<2><<<blocks, 256, 0, st>>>((const float4*)x, nrm, rp, csr, (float4*)y, N, F4, (const float4*)bias, dorelu);
        else              k_agg4<3><<<blocks, 256, 0, st>>>((const float4*)x, nrm, rp, csr, (float4*)y, N, F4, (const float4*)bias, dorelu);
        return;
    }
    if ((F & 1) == 0) {
        int F2 = F >> 1;
        int nj = gdiv(F2, 32);
        if (nj == 1)      k_agg2<1><<<blocks, 256, 0, st>>>((const float2*)x, nrm, rp, csr, (float2*)y, N, F2, (const float2*)bias, dorelu);
        else if (nj == 2) k_agg2<2><<<blocks, 256, 0, st>>>((const float2*)x, nrm, rp, csr, (float2*)y, N, F2, (const float2*)bias, dorelu);
        else              k_agg2<3><<<blocks, 256, 0, st>>>((const float2*)x, nrm, rp, csr, (float2*)y, N, F2, (const float2*)bias, dorelu);
        return;
    }
    int nf = gdiv(F, 32);
    switch (nf) {
        case 2: k_agg<2><<<blocks, 256, 0, st>>>(x, nrm, rp, csr, y, N, F, bias, dorelu); break;
        case 3: k_agg<3><<<blocks, 256, 0, st>>>(x, nrm, rp, csr, y, N, F, bias, dorelu); break;
        case 4: k_agg<4><<<blocks, 256, 0, st>>>(x, nrm, rp, csr, y, N, F, bias, dorelu); break;
        case 5: k_agg<5><<<blocks, 256, 0, st>>>(x, nrm, rp, csr, y, N, F, bias, dorelu); break;
        default: k_agg<8><<<blocks, 256, 0, st>>>(x, nrm, rp, csr, y, N, F, bias, dorelu); break;
    }
}

// ---------------- mean pool over contiguous per-graph ranges ----------------
__global__ void k_pool(const float* __restrict__ x, const int* __restrict__ gptr,
                       float* __restrict__ pool, int F) {
    int g = blockIdx.x;
    int beg = gptr[g], end = gptr[g + 1];
    float inv = 1.f / fmaxf((float)(end - beg), 1.f);
    for (int f = threadIdx.x; f < F; f += blockDim.x) {
        float s0 = 0.f, s1 = 0.f, s2 = 0.f, s3 = 0.f;
        int i = beg;
        for (; i + 3 < end; i += 4) {
            s0 += x[(size_t)(i + 0) * F + f];
            s1 += x[(size_t)(i + 1) * F + f];
            s2 += x[(size_t)(i + 2) * F + f];
            s3 += x[(size_t)(i + 3) * F + f];
        }
        for (; i < end; i++) s0 += x[(size_t)i * F + f];
        pool[(size_t)g * F + f] = (s0 + s1 + s2 + s3) * inv;
    }
}

// float4 pool (F % 4 == 0); F4 = F/4
__global__ void k_pool4(const float4* __restrict__ x, const int* __restrict__ gptr,
                        float4* __restrict__ pool, int F4) {
    int g = blockIdx.x;
    int beg = gptr[g], end = gptr[g + 1];
    float inv = 1.f / fmaxf((float)(end - beg), 1.f);
    for (int f = threadIdx.x; f < F4; f += blockDim.x) {
        float4 s0 = make_float4(0.f, 0.f, 0.f, 0.f);
        float4 s1 = make_float4(0.f, 0.f, 0.f, 0.f);
        int i = beg;
        for (; i + 1 < end; i += 2) {
            float4 a = x[(size_t)(i + 0) * F4 + f];
            float4 b = x[(size_t)(i + 1) * F4 + f];
            s0.x += a.x; s0.y += a.y; s0.z += a.z; s0.w += a.w;
            s1.x += b.x; s1.y += b.y; s1.z += b.z; s1.w += b.w;
        }
        if (i < end) {
            float4 a = x[(size_t)i * F4 + f];
            s0.x += a.x; s0.y += a.y; s0.z += a.z; s0.w += a.w;
        }
        float4 o;
        o.x = (s0.x + s1.x) * inv;
        o.y = (s0.y + s1.y) * inv;
        o.z = (s0.z + s1.z) * inv;
        o.w = (s0.w + s1.w) * inv;
        pool[(size_t)g * F4 + f] = o;
    }
}

// ---------------- SIMT SGEMM (templated tiles, double-buffered) ----------------
template <int MH, int NH>
__global__ __launch_bounds__(256) void k_sgemm(
    const float* __restrict__ A, const float* __restrict__ W,
    const float* __restrict__ bias, float* __restrict__ C,
    int N, int K, int M, int ldc, int relu)
{
    constexpr int TBM = 64 * MH;
    constexpr int TBN = 64 * NH;
    constexpr int CA = TBM / 32;
    constexpr int TPRA = 8 / CA;
    constexpr int CB = TBN / 32;

    __shared__ float As[2][8][TBM];
    __shared__ float Bs[2][8][TBN];

    int tid = threadIdx.x;
    int row0 = blockIdx.y * TBM;
    int col0 = blockIdx.x * TBN;
    int tx = tid & 15;
    int ty = tid >> 4;

    int a_r = tid / TPRA;
    int a_k = (tid % TPRA) * CA;
    int b_k = tid >> 5;
    int b_c = (tid & 31) * CB;

    int ar = row0 + a_r;
    const float* Arow = A + (size_t)(ar < N ? ar : 0) * K;
    bool a_ok = (ar < N);

    float acc[4 * MH][4 * NH];
#pragma unroll
    for (int i = 0; i < 4 * MH; i++)
#pragma unroll
        for (int j = 0; j < 4 * NH; j++) acc[i][j] = 0.f;

    float ra[CA], rb[CB];
    int kt = (K + 7) / 8;

#pragma unroll
    for (int i = 0; i < CA; i++) {
        int kc = a_k + i;
        ra[i] = (a_ok && kc < K) ? Arow[kc] : 0.f;
    }
#pragma unroll
    for (int i = 0; i < CB; i++) {
        int bc = col0 + b_c + i;
        rb[i] = (b_k < K && bc < M) ? W[(size_t)b_k * M + bc] : 0.f;
    }
#pragma unroll
    for (int i = 0; i < CA; i++) As[0][a_k + i][a_r] = ra[i];
#pragma unroll
    for (int i = 0; i < CB; i++) Bs[0][b_k][b_c + i] = rb[i];
    __syncthreads();

    int buf = 0;
    for (int t = 0; t < kt; t++) {
        int k_next = (t + 1) * 8;
        if (t + 1 < kt) {
#pragma unroll
            for (int i = 0; i < CA; i++) {
                int kc = k_next + a_k + i;
                ra[i] = (a_ok && kc < K) ? Arow[kc] : 0.f;
            }
            int bk = k_next + b_k;
#pragma unroll
            for (int i = 0; i < CB; i++) {
                int bc = col0 + b_c + i;
                rb[i] = (bk < K && bc < M) ? W[(size_t)bk * M + bc] : 0.f;
            }
        }

#pragma unroll
        for (int kk = 0; kk < 8; kk++) {
            float af[4 * MH], bf[4 * NH];
#pragma unroll
            for (int h = 0; h < MH; h++)
#pragma unroll
                for (int i = 0; i < 4; i++)
                    af[h * 4 + i] = As[buf][kk][h * 64 + ty * 4 + i];
#pragma unroll
            for (int h = 0; h < NH; h++)
#pragma unroll
                for (int j = 0; j < 4; j++)
                    bf[h * 4 + j] = Bs[buf][kk][h * 64 + tx * 4 + j];
#pragma unroll
            for (int i = 0; i < 4 * MH; i++)
#pragma unroll
                for (int j = 0; j < 4 * NH; j++) acc[i][j] += af[i] * bf[j];
        }

        if (t + 1 < kt) {
            int nb = buf ^ 1;
#pragma unroll
            for (int i = 0; i < CA; i++) As[nb][a_k + i][a_r] = ra[i];
#pragma unroll
            for (int i = 0; i < CB; i++) Bs[nb][b_k][b_c + i] = rb[i];
            __syncthreads();
            buf = nb;
        }
    }

#pragma unroll
    for (int hm = 0; hm < MH; hm++) {
#pragma unroll
        for (int i = 0; i < 4; i++) {
            int r = row0 + hm * 64 + ty * 4 + i;
            if (r >= N) continue;
#pragma unroll
            for (int hn = 0; hn < NH; hn++) {
#pragma unroll
                for (int j = 0; j < 4; j++) {
                    int c = col0 + hn * 64 + tx * 4 + j;
                    if (c >= M) continue;
                    float v = acc[hm * 4 + i][hn * 4 + j] + (bias ? bias[c] : 0.f);
                    if (relu) v = fmaxf(v, 0.f);
                    C[(size_t)r * ldc + c] = v;
                }
            }
        }
    }
}

// ---------------- split-K SGEMM: 64x64 tile, grid.z = K-chunks, writes partials ----
__global__ __launch_bounds__(256) void k_sgemm_sk(
    const float* __restrict__ A, const float* __restrict__ W,
    float* __restrict__ part, int N, int K, int M, int Kc)
{
    __shared__ float As[2][8][64];
    __shared__ float Bs[2][8][64];

    int tid = threadIdx.x;
    int row0 = blockIdx.y * 64;
    int col0 = blockIdx.x * 64;
    int z = blockIdx.z;
    int k0 = z * Kc;
    int kEff = K - k0; if (kEff > Kc) kEff = Kc;
    int tx = tid & 15;
    int ty = tid >> 4;

    int a_r = tid >> 2;
    int a_k = (tid & 3) * 2;
    int b_k = tid >> 5;
    int b_c = (tid & 31) * 2;

    int ar = row0 + a_r;
    const float* Arow = A + (size_t)(ar < N ? ar : 0) * K + k0;
    bool a_ok = (ar < N);

    float acc[4][4];
#pragma unroll
    for (int i = 0; i < 4; i++)
#pragma unroll
        for (int j = 0; j < 4; j++) acc[i][j] = 0.f;

    float ra[2], rb[2];
    int kt = (kEff + 7) / 8;

#pragma unroll
    for (int i = 0; i < 2; i++) {
        int kc = a_k + i;
        ra[i] = (a_ok && kc < kEff) ? Arow[kc] : 0.f;
    }
#pragma unroll
    for (int i = 0; i < 2; i++) {
        int bc = col0 + b_c + i;
        rb[i] = (b_k < kEff && bc < M) ? W[(size_t)(k0 + b_k) * M + bc] : 0.f;
    }
#pragma unroll
    for (int i = 0; i < 2; i++) As[0][a_k + i][a_r] = ra[i];
#pragma unroll
    for (int i = 0; i < 2; i++) Bs[0][b_k][b_c + i] = rb[i];
    __syncthreads();

    int buf = 0;
    for (int t = 0; t < kt; t++) {
        int k_next = (t + 1) * 8;
        if (t + 1 < kt) {
#pragma unroll
            for (int i = 0; i < 2; i++) {
                int kc = k_next + a_k + i;
                ra[i] = (a_ok && kc < kEff) ? Arow[kc] : 0.f;
            }
            int bk = k_next + b_k;
#pragma unroll
            for (int i = 0; i < 2; i++) {
                int bc = col0 + b_c + i;
                rb[i] = (bk < kEff && bc < M) ? W[(size_t)(k0 + bk) * M + bc] : 0.f;
            }
        }

#pragma unroll
        for (int kk = 0; kk < 8; kk++) {
            float af[4], bf[4];
#pragma unroll
            for (int i = 0; i < 4; i++) {
                af[i] = As[buf][kk][ty * 4 + i];
                bf[i] = Bs[buf][kk][tx * 4 + i];
            }
#pragma unroll
            for (int i = 0; i < 4; i++)
#pragma unroll
                for (int j = 0; j < 4; j++) acc[i][j] += af[i] * bf[j];
        }

        if (t + 1 < kt) {
            int nb = buf ^ 1;
#pragma unroll
            for (int i = 0; i < 2; i++) As[nb][a_k + i][a_r] = ra[i];
#pragma unroll
            for (int i = 0; i < 2; i++) Bs[nb][b_k][b_c + i] = rb[i];
            __syncthreads();
            buf = nb;
        }
    }

    float* P = part + (size_t)z * N * M;
#pragma unroll
    for (int i = 0; i < 4; i++) {
        int r = row0 + ty * 4 + i;
        if (r >= N) continue;
#pragma unroll
        for (int j = 0; j < 4; j++) {
            int c = col0 + tx * 4 + j;
            if (c >= M) continue;
            P[(size_t)r * M + c] = acc[i][j];
        }
    }
}

// deterministic fixed-order reduce of KS partials, + bias/relu
__global__ void k_red(const float* __restrict__ part, const float* __restrict__ bias,
                      float* __restrict__ C, int N, int M, int ldc, int relu, int KS) {
    int i = blockIdx.x * blockDim.x + threadIdx.x;
    if (i >= N * M) return;
    float s = 0.f;
    for (int z = 0; z < KS; z++) s += part[(size_t)z * N * M + i];
    int r = i / M, c = i - r * M;
    float v = s + (bias ? bias[c] : 0.f);
    if (relu) v = fmaxf(v, 0.f);
    C[(size_t)r * ldc + c] = v;
}

static void launch_sgemm(const float* A, const float* W, const float* bias, float* C,
                         int N, int K, int M, int ldc, int relu, cudaStream_t st,
                         float* part = nullptr) {
    if (part && N <= 256 && K >= 192) {
        int KS = 8;
        int Kc = gdiv(K, KS);
        Kc = (Kc + 7) & ~7;
        KS = gdiv(K, Kc);
        dim3 grid(gdiv(M, 64), gdiv(N, 64), KS);
        k_sgemm_sk<<<grid, 256, 0, st>>>(A, W, part, N, K, M, Kc);
        k_red<<<gdiv(N * M, 256), 256, 0, st>>>(part, bias, C, N, M, ldc, relu, KS);
        return;
    }
    int best_bm = 128, best_bn = 128;
    double best_score = 1e30;
    for (int bm = 128; bm >= 64; bm -= 64) {
        for (int bn = 128; bn >= 64; bn -= 64) {
            double padw = (double)((long)gdiv(N, bm) * bm) * ((long)gdiv(M, bn) * bn);
            long ctas = (long)gdiv(N, bm) * gdiv(M, bn);
            double occ_pen = (ctas < 296) ? (296.0 / (double)ctas) : 1.0;
            double tile_pen = (bm == 64 ? 1.06 : 1.0) * (bn == 64 ? 1.06 : 1.0);
            double score = padw * occ_pen * tile_pen;
            if (score < best_score) { best_score = score; best_bm = bm; best_bn = bn; }
        }
    }
    dim3 grid(gdiv(M, best_bn), gdiv(N, best_bm));
    if (best_bm == 128 && best_bn == 128)      k_sgemm<2, 2><<<grid, 256, 0, st>>>(A, W, bias, C, N, K, M, ldc, relu);
    else if (best_bm == 128 && best_bn == 64)  k_sgemm<2, 1><<<grid, 256, 0, st>>>(A, W, bias, C, N, K, M, ldc, relu);
    else if (best_bm == 64 && best_bn == 128)  k_sgemm<1, 2><<<grid, 256, 0, st>>>(A, W, bias, C, N, K, M, ldc, relu);
    else                                       k_sgemm<1, 1><<<grid, 256, 0, st>>>(A, W, bias, C, N, K, M, ldc, relu);
}

// ---------------- branch orchestration ----------------
static void run_branch(const float* x0, const int* ei, int E, const int* bat, int N,
                       int F0, int F1, int F2, int F3,
                       const float* w1, const float* b1,
                       const float* w2, const float* b2,
                       const float* w3, const float* b3,
                       const float* fw1, const float* fb1,
                       const float* fw2, const float* fb2,
                       float* cat_ptr,
                       float* Y, float* A, float* Bf,
                       float* nrm, int* deg, int* cur, int* rowptr, int* csr,
                       int* bsum, int* gptr, float* pool, float* fc1, float* part,
                       cudaStream_t st)
{
    const int* src = ei;
    const int* dst = ei + E;
    const int T = 256;
    int nb = gdiv(N, 1024);

    k_zeroi<<<gdiv(N, T), T, 0, st>>>(deg, N);
    k_hist<<<gdiv(E, T), T, 0, st>>>(dst, deg, E);
    k_scan_blk<<<nb, 1024, 0, st>>>(deg, rowptr, bsum, N);
    launch_sgemm(x0, w1, nullptr, Y, N, F0, F1, F1, 0, st);
    k_scan_small<<<1, 128, 0, st>>>(bsum, nb);
    k_scan_add<<<gdiv(N, T), T, 0, st>>>(rowptr, bsum, deg, nrm, cur, N, nb);
    k_fill<<<gdiv(E, T), T, 0, st>>>(src, dst, rowptr, cur, csr, E);

    // layer 1 epilogue: A = relu(nrm*(agg(Y) + nrm*Y) + b1)
    launch_agg(Y, nrm, rowptr, csr, A, N, F1, b1, 1, st);

    // layer 2
    launch_agg(A, nrm, rowptr, csr, Y, N, F1, nullptr, 0, st);
    launch_sgemm(Y, w2, b2, Bf, N, F1, F2, F2, 1, st);

    // layer 3
    launch_agg(Bf, nrm, rowptr, csr, Y, N, F2, nullptr, 0, st);
    launch_sgemm(Y, w3, b3, A, N, F2, F3, F3, 1, st);

    // mean pool (batch sorted -> contiguous ranges)
    k_ghist<<<1, 1024, 0, st>>>(bat, gptr, N);
    if ((F3 & 3) == 0)
        k_pool4<<<256, 256, 0, st>>>((const float4*)A, gptr, (float4*)pool, F3 >> 2);
    else
        k_pool<<<256, 256, 0, st>>>(A, gptr, pool, F3);

    // fc1 (split-K, relu), fc2 (split-K) -> concat slice (ldc=256)
    launch_sgemm(pool, fw1, fb1, fc1, 256, F3, 1024, 1024, 1, st, part);
    launch_sgemm(fc1, fw2, fb2, cat_ptr, 256, 1024, 128, 256, 0, st, part);
}

extern "C" void kernel_launch(void* const* d_in, const int* in_sizes, int n_in,
                              void* d_out, int out_size)
{
    static cudaStream_t s2 = nullptr;
    static cudaEvent_t evFork = nullptr, evJoin = nullptr;
    if (!s2) {
        cudaStreamCreateWithFlags(&s2, cudaStreamNonBlocking);
        cudaEventCreateWithFlags(&evFork, cudaEventDisableTiming);
        cudaEventCreateWithFlags(&evJoin, cudaEventDisableTiming);
    }

    float *Y, *A, *Bf, *nrm, *pool, *fc1, *part;
    int *deg, *cur, *rowptr, *csr, *bsum, *gptr;
    float *mY, *mA, *mBf, *mnrm, *mpool, *mfc1, *mpart;
    int *mdeg, *mcur, *mrowptr, *mcsr, *mbsum, *mgptr;
    float *cat, *head;
    cudaGetSymbolAddress((void**)&Y,       g_Y);
    cudaGetSymbolAddress((void**)&A,       g_A);
    cudaGetSymbolAddress((void**)&Bf,      g_B);
    cudaGetSymbolAddress((void**)&nrm,     g_nrm);
    cudaGetSymbolAddress((void**)&deg,     g_deg);
    cudaGetSymbolAddress((void**)&cur,     g_cur);
    cudaGetSymbolAddress((void**)&rowptr,  g_rowptr);
    cudaGetSymbolAddress((void**)&csr,     g_csr);
    cudaGetSymbolAddress((void**)&bsum,    g_bsum);
    cudaGetSymbolAddress((void**)&gptr,    g_gptr);
    cudaGetSymbolAddress((void**)&pool,    g_pool);
    cudaGetSymbolAddress((void**)&fc1,     g_fc1);
    cudaGetSymbolAddress((void**)&part,    g_part);
    cudaGetSymbolAddress((void**)&mY,      m_Y);
    cudaGetSymbolAddress((void**)&mA,      m_A);
    cudaGetSymbolAddress((void**)&mBf,     m_B);
    cudaGetSymbolAddress((void**)&mnrm,    m_nrm);
    cudaGetSymbolAddress((void**)&mdeg,    m_deg);
    cudaGetSymbolAddress((void**)&mcur,    m_cur);
    cudaGetSymbolAddress((void**)&mrowptr, m_rowptr);
    cudaGetSymbolAddress((void**)&mcsr,    m_csr);
    cudaGetSymbolAddress((void**)&mbsum,   m_bsum);
    cudaGetSymbolAddress((void**)&mgptr,   m_gptr);
    cudaGetSymbolAddress((void**)&mpool,   m_pool);
    cudaGetSymbolAddress((void**)&mfc1,    m_fc1);
    cudaGetSymbolAddress((void**)&mpart,   m_part);
    cudaGetSymbolAddress((void**)&cat,     g_cat);
    cudaGetSymbolAddress((void**)&head,    g_head);

    const float* mol_x  = (const float*)d_in[0];
    const int*   mol_ei = (const int*)  d_in[1];
    const int*   mol_b  = (const int*)  d_in[2];
    const float* pro_x  = (const float*)d_in[3];
    const int*   pro_ei = (const int*)  d_in[4];
    const int*   pro_b  = (const int*)  d_in[5];

    int N_mol = in_sizes[2];
    int E_mol = in_sizes[1] / 2;
    int F_mol = in_sizes[0] / N_mol;     // 78
    int N_pro = in_sizes[5];
    int E_pro = in_sizes[4] / 2;
    int F_pro = in_sizes[3] / N_pro;     // 54

    const float* mw1  = (const float*)d_in[6];
    const float* mb1  = (const float*)d_in[7];
    const float* mw2  = (const float*)d_in[8];
    const float* mb2  = (const float*)d_in[9];
    const float* mw3  = (const float*)d_in[10];
    const float* mb3  = (const float*)d_in[11];
    const float* mfw1 = (const float*)d_in[12];
    const float* mfb1 = (const float*)d_in[13];
    const float* mfw2 = (const float*)d_in[14];
    const float* mfb2 = (const float*)d_in[15];
    const float* pw1  = (const float*)d_in[16];
    const float* pb1  = (const float*)d_in[17];
    const float* pw2  = (const float*)d_in[18];
    const float* pb2  = (const float*)d_in[19];
    const float* pw3  = (const float*)d_in[20];
    const float* pb3  = (const float*)d_in[21];
    const float* pfw1 = (const float*)d_in[22];
    const float* pfb1 = (const float*)d_in[23];
    const float* pfw2 = (const float*)d_in[24];
    const float* pfb2 = (const float*)d_in[25];
    const float* fc1w = (const float*)d_in[26];
    const float* fc1b = (const float*)d_in[27];
    const float* fc2w = (const float*)d_in[28];
    const float* fc2b = (const float*)d_in[29];
    const float* outw = (const float*)d_in[30];
    const float* outb = (const float*)d_in[31];

    // fork: mol branch on s2, pro branch on legacy stream
    cudaEventRecord(evFork, 0);
    cudaStreamWaitEvent(s2, evFork, 0);

    run_branch(mol_x, mol_ei, E_mol, mol_b, N_mol,
               F_mol, F_mol, 2 * F_mol, 4 * F_mol,
               mw1, mb1, mw2, mb2, mw3, mb3,
               mfw1, mfb1, mfw2, mfb2,
               cat,
               mY, mA, mBf, mnrm, mdeg, mcur, mrowptr, mcsr,
               mbsum, mgptr, mpool, mfc1, mpart, s2);

    run_branch(pro_x, pro_ei, E_pro, pro_b, N_pro,
               F_pro, F_pro, 2 * F_pro, 4 * F_pro,
               pw1, pb1, pw2, pb2, pw3, pb3,
               pfw1, pfb1, pfw2, pfb2,
               cat + 128,
               Y, A, Bf, nrm, deg, cur, rowptr, csr,
               bsum, gptr, pool, fc1, part, 0);

    // join: head waits for mol branch
    cudaEventRecord(evJoin, s2);
    cudaStreamWaitEvent(0, evJoin, 0);

    // combined head (all split-K where K >= 192)
    launch_sgemm(cat,  fc1w, fc1b, fc1,           256, 256,  1024, 1024, 1, 0, part);
    launch_sgemm(fc1,  fc2w, fc2b, head,          256, 1024, 512,  512,  1, 0, part);
    launch_sgemm(head, outw, outb, (float*)d_out, 256, 512,  1,    1,    0, 0, part);
}

// round 16
// speedup vs baseline: 1.0609x; 1.0609x over previous
#include <cuda_runtime.h>
#include <math.h>
#include <stdint.h>

// ---------------- scratch (device globals; no allocations) ----------------
#define MAXN 76800
#define MAXE 768000
#define MAXNF (76800u * 216u)
#define MOLN 10240
#define MOLE 40960
#define MOLNF (10240u * 312u)

// protein-branch buffers
__device__ float g_Y[MAXNF];
__device__ float g_A[MAXNF];
__device__ float g_B[MAXNF];
__device__ float g_nrm[MAXN];
__device__ int   g_deg[MAXN];
__device__ int   g_cur[MAXN];
__device__ int   g_rowptr[MAXN + 1];
__device__ int   g_csr[MAXE];
__device__ int   g_bsum[128];
__device__ int   g_gptr[257];
__device__ float g_pool[256 * 312];
__device__ float g_fc1[256 * 1024];
__device__ float g_part[8 * 256 * 1024];
// molecule-branch buffers (private, for stream overlap)
__device__ float m_Y[MOLNF];
__device__ float m_A[MOLNF];
__device__ float m_B[MOLNF];
__device__ float m_nrm[MOLN];
__device__ int   m_deg[MOLN];
__device__ int   m_cur[MOLN];
__device__ int   m_rowptr[MOLN + 1];
__device__ int   m_csr[MOLE];
__device__ int   m_bsum[128];
__device__ int   m_gptr[257];
__device__ float m_pool[256 * 312];
__device__ float m_fc1[256 * 1024];
__device__ float m_part[8 * 256 * 1024];
// shared tail
__device__ float g_cat[256 * 256];
__device__ float g_head[256 * 512];

static inline int gdiv(int n, int d) { return (n + d - 1) / d; }

// ---------------- small utility kernels ----------------
__global__ void k_zeroi(int* a, int n) {
    int i = blockIdx.x * blockDim.x + threadIdx.x;
    if (i < n) a[i] = 0;
}

__global__ void k_hist(const int* __restrict__ idx, int* __restrict__ acc, int n) {
    int i = blockIdx.x * blockDim.x + threadIdx.x;
    if (i < n) atomicAdd(&acc[idx[i]], 1);
}

// ---- multi-block exclusive scan ----
__global__ void k_scan_blk(const int* __restrict__ in, int* __restrict__ out,
                           int* __restrict__ bsum, int n) {
    __shared__ int wsum[32];
    int tid = threadIdx.x;
    int lane = tid & 31, wid = tid >> 5;
    int i = blockIdx.x * 1024 + tid;
    int v = (i < n) ? in[i] : 0;
    int s = v;
#pragma unroll
    for (int off = 1; off < 32; off <<= 1) {
        int t = __shfl_up_sync(0xffffffffu, s, off);
        if (lane >= off) s += t;
    }
    if (lane == 31) wsum[wid] = s;
    __syncthreads();
    if (wid == 0) {
        int ws = wsum[lane];
#pragma unroll
        for (int off = 1; off < 32; off <<= 1) {
            int t = __shfl_up_sync(0xffffffffu, ws, off);
            if (lane >= off) ws += t;
        }
        wsum[lane] = ws;
    }
    __syncthreads();
    int wofs = (wid > 0) ? wsum[wid - 1] : 0;
    int incl = wofs + s;
    if (i < n) out[i] = incl - v;
    if (tid == 1023) bsum[blockIdx.x] = incl;
}

__global__ void k_scan_small(int* __restrict__ b, int nb) {
    __shared__ int wsum[4];
    int tid = threadIdx.x;
    int lane = tid & 31, wid = tid >> 5;
    int v = (tid < nb) ? b[tid] : 0;
    int s = v;
#pragma unroll
    for (int off = 1; off < 32; off <<= 1) {
        int t = __shfl_up_sync(0xffffffffu, s, off);
        if (lane >= off) s += t;
    }
    if (lane == 31) wsum[wid] = s;
    __syncthreads();
    if (tid == 0) {
        int c = 0;
        for (int w = 0; w < 4; w++) { int t = wsum[w]; wsum[w] = c; c += t; }
    }
    __syncthreads();
    int excl = wsum[wid] + s - v;
    __syncthreads();
    if (tid < nb) b[tid] = excl;
    if (tid == nb - 1) b[nb] = excl + v;
}

// phase 3 fused: add block offsets, compute nrm, zero cur
__global__ void k_scan_add(int* __restrict__ out, const int* __restrict__ bsum,
                           const int* __restrict__ deg, float* __restrict__ nrm,
                           int* __restrict__ cur, int n, int nb) {
    int i = blockIdx.x * blockDim.x + threadIdx.x;
    if (i < n) {
        out[i] += bsum[i >> 10];
        nrm[i] = rsqrtf((float)deg[i] + 1.f);
        cur[i] = 0;
    }
    if (i == 0) out[n] = bsum[nb];
}

// fused per-graph histogram + exclusive scan (256 graphs), single block 1024
__global__ void k_ghist(const int* __restrict__ bat, int* __restrict__ gptr, int n) {
    __shared__ int bins[256];
    __shared__ int wsum[8];
    int tid = threadIdx.x;
    int lane = tid & 31, wid = tid >> 5;
    if (tid < 256) bins[tid] = 0;
    __syncthreads();
    for (int i = tid; i < n; i += 1024) atomicAdd(&bins[bat[i]], 1);
    __syncthreads();
    int v = (tid < 256) ? bins[tid] : 0;
    int s = v;
#pragma unroll
    for (int off = 1; off < 32; off <<= 1) {
        int t = __shfl_up_sync(0xffffffffu, s, off);
        if (lane >= off) s += t;
    }
    if (lane == 31 && wid < 8) wsum[wid] = s;
    __syncthreads();
    if (tid == 0) {
        int c = 0;
        for (int w = 0; w < 8; w++) { int t = wsum[w]; wsum[w] = c; c += t; }
    }
    __syncthreads();
    if (tid < 256) {
        int excl = wsum[wid] + s - v;
        gptr[tid] = excl;
        if (tid == 255) gptr[256] = excl + v;
    }
}

__global__ void k_fill(const int* __restrict__ src, const int* __restrict__ dst,
                       const int* __restrict__ rowptr, int* __restrict__ cur,
                       int* __restrict__ csr, int E) {
    int e = blockIdx.x * blockDim.x + threadIdx.x;
    if (e >= E) return;
    int d = dst[e];
    int p = rowptr[d] + atomicAdd(&cur[d], 1);
    csr[p] = src[e];
}

// ---------------- aggregation: y_i = nrm_i*(sum nrm_s x_s + nrm_i x_i) [+bias][relu]
template <int NF>
__global__ void k_agg(const float* __restrict__ x, const float* __restrict__ nrm,
                      const int* __restrict__ rowptr, const int* __restrict__ csr,
                      float* __restrict__ y, int N, int F,
                      const float* __restrict__ bias, int dorelu) {
    int warp = (blockIdx.x * blockDim.x + threadIdx.x) >> 5;
    int lane = threadIdx.x & 31;
    if (warp >= N) return;
    int beg = rowptr[warp], end = rowptr[warp + 1];
    float ni = nrm[warp];

    float acc[NF];
#pragma unroll
    for (int j = 0; j < NF; j++) acc[j] = 0.f;

    int e = beg;
    for (; e + 1 < end; e += 2) {
        int s0 = csr[e], s1 = csr[e + 1];
        float n0 = nrm[s0], n1 = nrm[s1];
        const float* x0 = x + (size_t)s0 * F;
        const float* x1 = x + (size_t)s1 * F;
#pragma unroll
        for (int j = 0; j < NF; j++) {
            int f = lane + 32 * j;
            if (f < F) acc[j] += x0[f] * n0 + x1[f] * n1;
        }
    }
    if (e < end) {
        int s0 = csr[e];
        float n0 = nrm[s0];
        const float* x0 = x + (size_t)s0 * F;
#pragma unroll
        for (int j = 0; j < NF; j++) {
            int f = lane + 32 * j;
            if (f < F) acc[j] += x0[f] * n0;
        }
    }
    const float* xi = x + (size_t)warp * F;
    float* yi = y + (size_t)warp * F;
#pragma unroll
    for (int j = 0; j < NF; j++) {
        int f = lane + 32 * j;
        if (f < F) {
            float v = ni * (acc[j] + ni * xi[f]);
            if (bias) v += bias[f];
            if (dorelu) v = fmaxf(v, 0.f);
            yi[f] = v;
        }
    }
}

// float2 variant (F % 2 == 0); F2 = F/2; 4-edge unroll
template <int NJ>
__global__ void k_agg2(const float2* __restrict__ x, const float* __restrict__ nrm,
                       const int* __restrict__ rowptr, const int* __restrict__ csr,
                       float2* __restrict__ y, int N, int F2,
                       const float2* __restrict__ bias, int dorelu) {
    int warp = (blockIdx.x * blockDim.x + threadIdx.x) >> 5;
    int lane = threadIdx.x & 31;
    if (warp >= N) return;
    int beg = rowptr[warp], end = rowptr[warp + 1];
    float ni = nrm[warp];

    float2 acc[NJ];
#pragma unroll
    for (int j = 0; j < NJ; j++) acc[j] = make_float2(0.f, 0.f);

    int e = beg;
    for (; e + 3 < end; e += 4) {
        int s0 = csr[e], s1 = csr[e + 1], s2 = csr[e + 2], s3 = csr[e + 3];
        float n0 = nrm[s0], n1 = nrm[s1], n2 = nrm[s2], n3 = nrm[s3];
        const float2* x0 = x + (size_t)s0 * F2;
        const float2* x1 = x + (size_t)s1 * F2;
        const float2* x2 = x + (size_t)s2 * F2;
        const float2* x3 = x + (size_t)s3 * F2;
#pragma unroll
        for (int j = 0; j < NJ; j++) {
            int f = lane + 32 * j;
            if (f < F2) {
                float2 v0 = x0[f], v1 = x1[f], v2 = x2[f], v3 = x3[f];
                acc[j].x += v0.x * n0 + v1.x * n1 + v2.x * n2 + v3.x * n3;
                acc[j].y += v0.y * n0 + v1.y * n1 + v2.y * n2 + v3.y * n3;
            }
        }
    }
    for (; e < end; e++) {
        int s0 = csr[e];
        float n0 = nrm[s0];
        const float2* x0 = x + (size_t)s0 * F2;
#pragma unroll
        for (int j = 0; j < NJ; j++) {
            int f = lane + 32 * j;
            if (f < F2) {
                float2 v0 = x0[f];
                acc[j].x += v0.x * n0;
                acc[j].y += v0.y * n0;
            }
        }
    }
    const float2* xi = x + (size_t)warp * F2;
    float2* yi = y + (size_t)warp * F2;
#pragma unroll
    for (int j = 0; j < NJ; j++) {
        int f = lane + 32 * j;
        if (f < F2) {
            float2 v = xi[f];
            float2 o;
            o.x = ni * (acc[j].x + ni * v.x);
            o.y = ni * (acc[j].y + ni * v.y);
            if (bias) { float2 b = bias[f]; o.x += b.x; o.y += b.y; }
            if (dorelu) { o.x = fmaxf(o.x, 0.f); o.y = fmaxf(o.y, 0.f); }
            yi[f] = o;
        }
    }
}

// float4 variant (F % 4 == 0); F4 = F/4; 4-edge unroll
template <int NJ>
__global__ void k_agg4(const float4* __restrict__ x, const float* __restrict__ nrm,
                       const int* __restrict__ rowptr, const int* __restrict__ csr,
                       float4* __restrict__ y, int N, int F4,
                       const float4* __restrict__ bias, int dorelu) {
    int warp = (blockIdx.x * blockDim.x + threadIdx.x) >> 5;
    int lane = threadIdx.x & 31;
    if (warp >= N) return;
    int beg = rowptr[warp], end = rowptr[warp + 1];
    float ni = nrm[warp];

    float4 acc[NJ];
#pragma unroll
    for (int j = 0; j < NJ; j++) acc[j] = make_float4(0.f, 0.f, 0.f, 0.f);

    int e = beg;
    for (; e + 3 < end; e += 4) {
        int s0 = csr[e], s1 = csr[e + 1], s2 = csr[e + 2], s3 = csr[e + 3];
        float n0 = nrm[s0], n1 = nrm[s1], n2 = nrm[s2], n3 = nrm[s3];
        const float4* x0 = x + (size_t)s0 * F4;
        const float4* x1 = x + (size_t)s1 * F4;
        const float4* x2 = x + (size_t)s2 * F4;
        const float4* x3 = x + (size_t)s3 * F4;
#pragma unroll
        for (int j = 0; j < NJ; j++) {
            int f = lane + 32 * j;
            if (f < F4) {
                float4 v0 = x0[f], v1 = x1[f], v2 = x2[f], v3 = x3[f];
                acc[j].x += v0.x * n0 + v1.x * n1 + v2.x * n2 + v3.x * n3;
                acc[j].y += v0.y * n0 + v1.y * n1 + v2.y * n2 + v3.y * n3;
                acc[j].z += v0.z * n0 + v1.z * n1 + v2.z * n2 + v3.z * n3;
                acc[j].w += v0.w * n0 + v1.w * n1 + v2.w * n2 + v3.w * n3;
            }
        }
    }
    for (; e < end; e++) {
        int s0 = csr[e];
        float n0 = nrm[s0];
        const float4* x0 = x + (size_t)s0 * F4;
#pragma unroll
        for (int j = 0; j < NJ; j++) {
            int f = lane + 32 * j;
            if (f < F4) {
                float4 v0 = x0[f];
                acc[j].x += v0.x * n0;
                acc[j].y += v0.y * n0;
                acc[j].z += v0.z * n0;
                acc[j].w += v0.w * n0;
            }
        }
    }
    const float4* xi = x + (size_t)warp * F4;
    float4* yi = y + (size_t)warp * F4;
#pragma unroll
    for (int j = 0; j < NJ; j++) {
        int f = lane + 32 * j;
        if (f < F4) {
            float4 v = xi[f];
            float4 o;
            o.x = ni * (acc[j].x + ni * v.x);
            o.y = ni * (acc[j].y + ni * v.y);
            o.z = ni * (acc[j].z + ni * v.z);
            o.w = ni * (acc[j].w + ni * v.w);
            if (bias) {
                float4 b = bias[f];
                o.x += b.x; o.y += b.y; o.z += b.z; o.w += b.w;
            }
            if (dorelu) {
                o.x = fmaxf(o.x, 0.f); o.y = fmaxf(o.y, 0.f);
                o.z = fmaxf(o.z, 0.f); o.w = fmaxf(o.w, 0.f);
            }
            yi[f] = o;
        }
    }
}

static void launch_agg(const float* x, const float* nrm, const int* rp, const int* csr,
                       float* y, int N, int F, const float* bias, int dorelu,
                       cudaStream_t st) {
    int blocks = gdiv(N, 8);
    if ((F & 3) == 0) {
        int F4 = F >> 2;
        int nj = gdiv(F4, 32);
        if (nj == 1)      k_agg4<1><<<blocks, 256, 0, st>>>((const float4*)x, nrm, rp, csr, (float4*)y, N, F4, (const float4*)bias, dorelu);
        else if (nj == 2) k_agg4<2><<<blocks, 256, 0, st>>>((const float4*)x, nrm, rp, csr, (float4*)y, N, F4, (const float4*)bias, dorelu);
        else              k_agg4<3><<<blocks, 256, 0, st>>>((const float4*)x, nrm, rp, csr, (float4*)y, N, F4, (const float4*)bias, dorelu);
        return;
    }
    if ((F & 1) == 0) {
        int F2 = F >> 1;
        int nj = gdiv(F2, 32);
        if (nj == 1)      k_agg2<1><<<blocks, 256, 0, st>>>((const float2*)x, nrm, rp, csr, (float2*)y, N, F2, (const float2*)bias, dorelu);
        else if (nj == 2) k_agg2<2><<<blocks, 256, 0, st>>>((const float2*)x, nrm, rp, csr, (float2*)y, N, F2, (const float2*)bias, dorelu);
        else              k_agg2<3><<<blocks, 256, 0, st>>>((const float2*)x, nrm, rp, csr, (float2*)y, N, F2, (const float2*)bias, dorelu);
        return;
    }
    int nf = gdiv(F, 32);
    switch (nf) {
        case 2: k_agg<2><<<blocks, 256, 0, st>>>(x, nrm, rp, csr, y, N, F, bias, dorelu); break;
        case 3: k_agg<3><<<blocks, 256, 0, st>>>(x, nrm, rp, csr, y, N, F, bias, dorelu); break;
        case 4: k_agg<4><<<blocks, 256, 0, st>>>(x, nrm, rp, csr, y, N, F, bias, dorelu); break;
        case 5: k_agg<5><<<blocks, 256, 0, st>>>(x, nrm, rp, csr, y, N, F, bias, dorelu); break;
        default: k_agg<8><<<blocks, 256, 0, st>>>(x, nrm, rp, csr, y, N, F, bias, dorelu); break;
    }
}

// ---------------- mean pool over contiguous per-graph ranges ----------------
__global__ void k_pool(const float* __restrict__ x, const int* __restrict__ gptr,
                       float* __restrict__ pool, int F) {
    int g = blockIdx.x;
    int beg = gptr[g], end = gptr[g + 1];
    float inv = 1.f / fmaxf((float)(end - beg), 1.f);
    for (int f = threadIdx.x; f < F; f += blockDim.x) {
        float s0 = 0.f, s1 = 0.f, s2 = 0.f, s3 = 0.f;
        int i = beg;
        for (; i + 3 < end; i += 4) {
            s0 += x[(size_t)(i + 0) * F + f];
            s1 += x[(size_t)(i + 1) * F + f];
            s2 += x[(size_t)(i + 2) * F + f];
            s3 += x[(size_t)(i + 3) * F + f];
        }
        for (; i < end; i++) s0 += x[(size_t)i * F + f];
        pool[(size_t)g * F + f] = (s0 + s1 + s2 + s3) * inv;
    }
}

// ---------------- SIMT SGEMM (templated tiles, double-buffered) ----------------
template <int MH, int NH>
__global__ __launch_bounds__(256) void k_sgemm(
    const float* __restrict__ A, const float* __restrict__ W,
    const float* __restrict__ bias, float* __restrict__ C,
    int N, int K, int M, int ldc, int relu)
{
    constexpr int TBM = 64 * MH;
    constexpr int TBN = 64 * NH;
    constexpr int CA = TBM / 32;
    constexpr int TPRA = 8 / CA;
    constexpr int CB = TBN / 32;

    __shared__ float As[2][8][TBM];
    __shared__ float Bs[2][8][TBN];

    int tid = threadIdx.x;
    int row0 = blockIdx.y * TBM;
    int col0 = blockIdx.x * TBN;
    int tx = tid & 15;
    int ty = tid >> 4;

    int a_r = tid / TPRA;
    int a_k = (tid % TPRA) * CA;
    int b_k = tid >> 5;
    int b_c = (tid & 31) * CB;

    int ar = row0 + a_r;
    const float* Arow = A + (size_t)(ar < N ? ar : 0) * K;
    bool a_ok = (ar < N);

    float acc[4 * MH][4 * NH];
#pragma unroll
    for (int i = 0; i < 4 * MH; i++)
#pragma unroll
        for (int j = 0; j < 4 * NH; j++) acc[i][j] = 0.f;

    float ra[CA], rb[CB];
    int kt = (K + 7) / 8;

#pragma unroll
    for (int i = 0; i < CA; i++) {
        int kc = a_k + i;
        ra[i] = (a_ok && kc < K) ? Arow[kc] : 0.f;
    }
#pragma unroll
    for (int i = 0; i < CB; i++) {
        int bc = col0 + b_c + i;
        rb[i] = (b_k < K && bc < M) ? W[(size_t)b_k * M + bc] : 0.f;
    }
#pragma unroll
    for (int i = 0; i < CA; i++) As[0][a_k + i][a_r] = ra[i];
#pragma unroll
    for (int i = 0; i < CB; i++) Bs[0][b_k][b_c + i] = rb[i];
    __syncthreads();

    int buf = 0;
    for (int t = 0; t < kt; t++) {
        int k_next = (t + 1) * 8;
        if (t + 1 < kt) {
#pragma unroll
            for (int i = 0; i < CA; i++) {
                int kc = k_next + a_k + i;
                ra[i] = (a_ok && kc < K) ? Arow[kc] : 0.f;
            }
            int bk = k_next + b_k;
#pragma unroll
            for (int i = 0; i < CB; i++) {
                int bc = col0 + b_c + i;
                rb[i] = (bk < K && bc < M) ? W[(size_t)bk * M + bc] : 0.f;
            }
        }

#pragma unroll
        for (int kk = 0; kk < 8; kk++) {
            float af[4 * MH], bf[4 * NH];
#pragma unroll
            for (int h = 0; h < MH; h++)
#pragma unroll
                for (int i = 0; i < 4; i++)
                    af[h * 4 + i] = As[buf][kk][h * 64 + ty * 4 + i];
#pragma unroll
            for (int h = 0; h < NH; h++)
#pragma unroll
                for (int j = 0; j < 4; j++)
                    bf[h * 4 + j] = Bs[buf][kk][h * 64 + tx * 4 + j];
#pragma unroll
            for (int i = 0; i < 4 * MH; i++)
#pragma unroll
                for (int j = 0; j < 4 * NH; j++) acc[i][j] += af[i] * bf[j];
        }

        if (t + 1 < kt) {
            int nb = buf ^ 1;
#pragma unroll
            for (int i = 0; i < CA; i++) As[nb][a_k + i][a_r] = ra[i];
#pragma unroll
            for (int i = 0; i < CB; i++) Bs[nb][b_k][b_c + i] = rb[i];
            __syncthreads();
            buf = nb;
        }
    }

#pragma unroll
    for (int hm = 0; hm < MH; hm++) {
#pragma unroll
        for (int i = 0; i < 4; i++) {
            int r = row0 + hm * 64 + ty * 4 + i;
            if (r >= N) continue;
#pragma unroll
            for (int hn = 0; hn < NH; hn++) {
#pragma unroll
                for (int j = 0; j < 4; j++) {
                    int c = col0 + hn * 64 + tx * 4 + j;
                    if (c >= M) continue;
                    float v = acc[hm * 4 + i][hn * 4 + j] + (bias ? bias[c] : 0.f);
                    if (relu) v = fmaxf(v, 0.f);
                    C[(size_t)r * ldc + c] = v;
                }
            }
        }
    }
}

// ---------------- split-K SGEMM: 64x64 tile, grid.z = K-chunks, writes partials ----
__global__ __launch_bounds__(256) void k_sgemm_sk(
    const float* __restrict__ A, const float* __restrict__ W,
    float* __restrict__ part, int N, int K, int M, int Kc)
{
    __shared__ float As[2][8][64];
    __shared__ float Bs[2][8][64];

    int tid = threadIdx.x;
    int row0 = blockIdx.y * 64;
    int col0 = blockIdx.x * 64;
    int z = blockIdx.z;
    int k0 = z * Kc;
    int kEff = K - k0; if (kEff > Kc) kEff = Kc;
    int tx = tid & 15;
    int ty = tid >> 4;

    int a_r = tid >> 2;
    int a_k = (tid & 3) * 2;
    int b_k = tid >> 5;
    int b_c = (tid & 31) * 2;

    int ar = row0 + a_r;
    const float* Arow = A + (size_t)(ar < N ? ar : 0) * K + k0;
    bool a_ok = (ar < N);

    float acc[4][4];
#pragma unroll
    for (int i = 0; i < 4; i++)
#pragma unroll
        for (int j = 0; j < 4; j++) acc[i][j] = 0.f;

    float ra[2], rb[2];
    int kt = (kEff + 7) / 8;

#pragma unroll
    for (int i = 0; i < 2; i++) {
        int kc = a_k + i;
        ra[i] = (a_ok && kc < kEff) ? Arow[kc] : 0.f;
    }
#pragma unroll
    for (int i = 0; i < 2; i++) {
        int bc = col0 + b_c + i;
        rb[i] = (b_k < kEff && bc < M) ? W[(size_t)(k0 + b_k) * M + bc] : 0.f;
    }
#pragma unroll
    for (int i = 0; i < 2; i++) As[0][a_k + i][a_r] = ra[i];
#pragma unroll
    for (int i = 0; i < 2; i++) Bs[0][b_k][b_c + i] = rb[i];
    __syncthreads();

    int buf = 0;
    for (int t = 0; t < kt; t++) {
        int k_next = (t + 1) * 8;
        if (t + 1 < kt) {
#pragma unroll
            for (int i = 0; i < 2; i++) {
                int kc = k_next + a_k + i;
                ra[i] = (a_ok && kc < kEff) ? Arow[kc] : 0.f;
            }
            int bk = k_next + b_k;
#pragma unroll
            for (int i = 0; i < 2; i++) {
                int bc = col0 + b_c + i;
                rb[i] = (bk < kEff && bc < M) ? W[(size_t)(k0 + bk) * M + bc] : 0.f;
            }
        }

#pragma unroll
        for (int kk = 0; kk < 8; kk++) {
            float af[4], bf[4];
#pragma unroll
            for (int i = 0; i < 4; i++) {
                af[i] = As[buf][kk][ty * 4 + i];
                bf[i] = Bs[buf][kk][tx * 4 + i];
            }
#pragma unroll
            for (int i = 0; i < 4; i++)
#pragma unroll
                for (int j = 0; j < 4; j++) acc[i][j] += af[i] * bf[j];
        }

        if (t + 1 < kt) {
            int nb = buf ^ 1;
#pragma unroll
            for (int i = 0; i < 2; i++) As[nb][a_k + i][a_r] = ra[i];
#pragma unroll
            for (int i = 0; i < 2; i++) Bs[nb][b_k][b_c + i] = rb[i];
            __syncthreads();
            buf = nb;
        }
    }

    float* P = part + (size_t)z * N * M;
#pragma unroll
    for (int i = 0; i < 4; i++) {
        int r = row0 + ty * 4 + i;
        if (r >= N) continue;
#pragma unroll
        for (int j = 0; j < 4; j++) {
            int c = col0 + tx * 4 + j;
            if (c >= M) continue;
            P[(size_t)r * M + c] = acc[i][j];
        }
    }
}

// deterministic fixed-order reduce of KS partials, + bias/relu
__global__ void k_red(const float* __restrict__ part, const float* __restrict__ bias,
                      float* __restrict__ C, int N, int M, int ldc, int relu, int KS) {
    int i = blockIdx.x * blockDim.x + threadIdx.x;
    if (i >= N * M) return;
    float s = 0.f;
    for (int z = 0; z < KS; z++) s += part[(size_t)z * N * M + i];
    int r = i / M, c = i - r * M;
    float v = s + (bias ? bias[c] : 0.f);
    if (relu) v = fmaxf(v, 0.f);
    C[(size_t)r * ldc + c] = v;
}

static void launch_sgemm(const float* A, const float* W, const float* bias, float* C,
                         int N, int K, int M, int ldc, int relu, cudaStream_t st,
                         float* part = nullptr) {
    if (part && N <= 256 && K >= 192) {
        int KS = 8;
        int Kc = gdiv(K, KS);
        Kc = (Kc + 7) & ~7;
        KS = gdiv(K, Kc);
        dim3 grid(gdiv(M, 64), gdiv(N, 64), KS);
        k_sgemm_sk<<<grid, 256, 0, st>>>(A, W, part, N, K, M, Kc);
        k_red<<<gdiv(N * M, 256), 256, 0, st>>>(part, bias, C, N, M, ldc, relu, KS);
        return;
    }
    int best_bm = 128, best_bn = 128;
    double best_score = 1e30;
    for (int bm = 128; bm >= 64; bm -= 64) {
        for (int bn = 128; bn >= 64; bn -= 64) {
            double padw = (double)((long)gdiv(N, bm) * bm) * ((long)gdiv(M, bn) * bn);
            long ctas = (long)gdiv(N, bm) * gdiv(M, bn);
            double occ_pen = (ctas < 296) ? (296.0 / (double)ctas) : 1.0;
            double tile_pen = (bm == 64 ? 1.06 : 1.0) * (bn == 64 ? 1.06 : 1.0);
            double score = padw * occ_pen * tile_pen;
            if (score < best_score) { best_score = score; best_bm = bm; best_bn = bn; }
        }
    }
    dim3 grid(gdiv(M, best_bn), gdiv(N, best_bm));
    if (best_bm == 128 && best_bn == 128)      k_sgemm<2, 2><<<grid, 256, 0, st>>>(A, W, bias, C, N, K, M, ldc, relu);
    else if (best_bm == 128 && best_bn == 64)  k_sgemm<2, 1><<<grid, 256, 0, st>>>(A, W, bias, C, N, K, M, ldc, relu);
    else if (best_bm == 64 && best_bn == 128)  k_sgemm<1, 2><<<grid, 256, 0, st>>>(A, W, bias, C, N, K, M, ldc, relu);
    else                                       k_sgemm<1, 1><<<grid, 256, 0, st>>>(A, W, bias, C, N, K, M, ldc, relu);
}

// ---------------- branch orchestration ----------------
static void run_branch(const float* x0, const int* ei, int E, const int* bat, int N,
                       int F0, int F1, int F2, int F3,
                       const float* w1, const float* b1,
                       const float* w2, const float* b2,
                       const float* w3, const float* b3,
                       const float* fw1, const float* fb1,
                       const float* fw2, const float* fb2,
                       float* cat_ptr,
                       float* Y, float* A, float* Bf,
                       float* nrm, int* deg, int* cur, int* rowptr, int* csr,
                       int* bsum, int* gptr, float* pool, float* fc1, float* part,
                       cudaStream_t st)
{
    const int* src = ei;
    const int* dst = ei + E;
    const int T = 256;
    int nb = gdiv(N, 1024);

    k_zeroi<<<gdiv(N, T), T, 0, st>>>(deg, N);
    k_hist<<<gdiv(E, T), T, 0, st>>>(dst, deg, E);
    k_scan_blk<<<nb, 1024, 0, st>>>(deg, rowptr, bsum, N);
    launch_sgemm(x0, w1, nullptr, Y, N, F0, F1, F1, 0, st);
    k_scan_small<<<1, 128, 0, st>>>(bsum, nb);
    k_scan_add<<<gdiv(N, T), T, 0, st>>>(rowptr, bsum, deg, nrm, cur, N, nb);
    k_fill<<<gdiv(E, T), T, 0, st>>>(src, dst, rowptr, cur, csr, E);

    // layer 1 epilogue: A = relu(nrm*(agg(Y) + nrm*Y) + b1)
    launch_agg(Y, nrm, rowptr, csr, A, N, F1, b1, 1, st);

    // layer 2
    launch_agg(A, nrm, rowptr, csr, Y, N, F1, nullptr, 0, st);
    launch_sgemm(Y, w2, b2, Bf, N, F1, F2, F2, 1, st);

    // layer 3
    launch_agg(Bf, nrm, rowptr, csr, Y, N, F2, nullptr, 0, st);
    launch_sgemm(Y, w3, b3, A, N, F2, F3, F3, 1, st);

    // mean pool (batch sorted -> contiguous ranges)
    k_ghist<<<1, 1024, 0, st>>>(bat, gptr, N);
    k_pool<<<256, 256, 0, st>>>(A, gptr, pool, F3);

    // fc1 (split-K, relu), fc2 (split-K) -> concat slice (ldc=256)
    launch_sgemm(pool, fw1, fb1, fc1, 256, F3, 1024, 1024, 1, st, part);
    launch_sgemm(fc1, fw2, fb2, cat_ptr, 256, 1024, 128, 256, 0, st, part);
}

extern "C" void kernel_launch(void* const* d_in, const int* in_sizes, int n_in,
                              void* d_out, int out_size)
{
    static cudaStream_t s2 = nullptr;
    static cudaEvent_t evFork = nullptr, evJoin = nullptr;
    if (!s2) {
        cudaStreamCreateWithFlags(&s2, cudaStreamNonBlocking);
        cudaEventCreateWithFlags(&evFork, cudaEventDisableTiming);
        cudaEventCreateWithFlags(&evJoin, cudaEventDisableTiming);
    }

    float *Y, *A, *Bf, *nrm, *pool, *fc1, *part;
    int *deg, *cur, *rowptr, *csr, *bsum, *gptr;
    float *mY, *mA, *mBf, *mnrm, *mpool, *mfc1, *mpart;
    int *mdeg, *mcur, *mrowptr, *mcsr, *mbsum, *mgptr;
    float *cat, *head;
    cudaGetSymbolAddress((void**)&Y,       g_Y);
    cudaGetSymbolAddress((void**)&A,       g_A);
    cudaGetSymbolAddress((void**)&Bf,      g_B);
    cudaGetSymbolAddress((void**)&nrm,     g_nrm);
    cudaGetSymbolAddress((void**)&deg,     g_deg);
    cudaGetSymbolAddress((void**)&cur,     g_cur);
    cudaGetSymbolAddress((void**)&rowptr,  g_rowptr);
    cudaGetSymbolAddress((void**)&csr,     g_csr);
    cudaGetSymbolAddress((void**)&bsum,    g_bsum);
    cudaGetSymbolAddress((void**)&gptr,    g_gptr);
    cudaGetSymbolAddress((void**)&pool,    g_pool);
    cudaGetSymbolAddress((void**)&fc1,     g_fc1);
    cudaGetSymbolAddress((void**)&part,    g_part);
    cudaGetSymbolAddress((void**)&mY,      m_Y);
    cudaGetSymbolAddress((void**)&mA,      m_A);
    cudaGetSymbolAddress((void**)&mBf,     m_B);
    cudaGetSymbolAddress((void**)&mnrm,    m_nrm);
    cudaGetSymbolAddress((void**)&mdeg,    m_deg);
    cudaGetSymbolAddress((void**)&mcur,    m_cur);
    cudaGetSymbolAddress((void**)&mrowptr, m_rowptr);
    cudaGetSymbolAddress((void**)&mcsr,    m_csr);
    cudaGetSymbolAddress((void**)&mbsum,   m_bsum);
    cudaGetSymbolAddress((void**)&mgptr,   m_gptr);
    cudaGetSymbolAddress((void**)&mpool,   m_pool);
    cudaGetSymbolAddress((void**)&mfc1,    m_fc1);
    cudaGetSymbolAddress((void**)&mpart,   m_part);
    cudaGetSymbolAddress((void**)&cat,     g_cat);
    cudaGetSymbolAddress((void**)&head,    g_head);

    const float* mol_x  = (const float*)d_in[0];
    const int*   mol_ei = (const int*)  d_in[1];
    const int*   mol_b  = (const int*)  d_in[2];
    const float* pro_x  = (const float*)d_in[3];
    const int*   pro_ei = (const int*)  d_in[4];
    const int*   pro_b  = (const int*)  d_in[5];

    int N_mol = in_sizes[2];
    int E_mol = in_sizes[1] / 2;
    int F_mol = in_sizes[0] / N_mol;     // 78
    int N_pro = in_sizes[5];
    int E_pro = in_sizes[4] / 2;
    int F_pro = in_sizes[3] / N_pro;     // 54

    const float* mw1  = (const float*)d_in[6];
    const float* mb1  = (const float*)d_in[7];
    const float* mw2  = (const float*)d_in[8];
    const float* mb2  = (const float*)d_in[9];
    const float* mw3  = (const float*)d_in[10];
    const float* mb3  = (const float*)d_in[11];
    const float* mfw1 = (const float*)d_in[12];
    const float* mfb1 = (const float*)d_in[13];
    const float* mfw2 = (const float*)d_in[14];
    const float* mfb2 = (const float*)d_in[15];
    const float* pw1  = (const float*)d_in[16];
    const float* pb1  = (const float*)d_in[17];
    const float* pw2  = (const float*)d_in[18];
    const float* pb2  = (const float*)d_in[19];
    const float* pw3  = (const float*)d_in[20];
    const float* pb3  = (const float*)d_in[21];
    const float* pfw1 = (const float*)d_in[22];
    const float* pfb1 = (const float*)d_in[23];
    const float* pfw2 = (const float*)d_in[24];
    const float* pfb2 = (const float*)d_in[25];
    const float* fc1w = (const float*)d_in[26];
    const float* fc1b = (const float*)d_in[27];
    const float* fc2w = (const float*)d_in[28];
    const float* fc2b = (const float*)d_in[29];
    const float* outw = (const float*)d_in[30];
    const float* outb = (const float*)d_in[31];

    // fork: mol branch on s2, pro branch on legacy stream
    cudaEventRecord(evFork, 0);
    cudaStreamWaitEvent(s2, evFork, 0);

    run_branch(mol_x, mol_ei, E_mol, mol_b, N_mol,
               F_mol, F_mol, 2 * F_mol, 4 * F_mol,
               mw1, mb1, mw2, mb2, mw3, mb3,
               mfw1, mfb1, mfw2, mfb2,
               cat,
               mY, mA, mBf, mnrm, mdeg, mcur, mrowptr, mcsr,
               mbsum, mgptr, mpool, mfc1, mpart, s2);

    run_branch(pro_x, pro_ei, E_pro, pro_b, N_pro,
               F_pro, F_pro, 2 * F_pro, 4 * F_pro,
               pw1, pb1, pw2, pb2, pw3, pb3,
               pfw1, pfb1, pfw2, pfb2,
               cat + 128,
               Y, A, Bf, nrm, deg, cur, rowptr, csr,
               bsum, gptr, pool, fc1, part, 0);

    // join: head waits for mol branch
    cudaEventRecord(evJoin, s2);
    cudaStreamWaitEvent(0, evJoin, 0);

    // combined head (all split-K where K >= 192)
    launch_sgemm(cat,  fc1w, fc1b, fc1,           256, 256,  1024, 1024, 1, 0, part);
    launch_sgemm(fc1,  fc2w, fc2b, head,          256, 1024, 512,  512,  1, 0, part);
    launch_sgemm(head, outw, outb, (float*)d_out, 256, 512,  1,    1,    0, 0, part);
}

// round 17
// speedup vs baseline: 1.0656x; 1.0045x over previous
#include <cuda_runtime.h>
#include <math.h>
#include <stdint.h>

// ---------------- scratch (device globals; no allocations) ----------------
#define MAXN 76800
#define MAXE 768000
#define MAXNF (76800u * 216u)
#define MOLN 10240
#define MOLE 40960
#define MOLNF (10240u * 312u)

// protein-branch buffers
__device__ float g_Y[MAXNF];
__device__ float g_A[MAXNF];
__device__ float g_B[MAXNF];
__device__ float g_nrm[MAXN];
__device__ int   g_deg[MAXN];
__device__ int   g_cur[MAXN];
__device__ int   g_rowptr[MAXN + 1];
__device__ int   g_csr[MAXE];
__device__ int   g_bsum[128];
__device__ int   g_gptr[257];
__device__ float g_pool[256 * 312];
__device__ float g_fc1[256 * 1024];
__device__ float g_part[8 * 256 * 1024];
// molecule-branch buffers (private, for stream overlap)
__device__ float m_Y[MOLNF];
__device__ float m_A[MOLNF];
__device__ float m_B[MOLNF];
__device__ float m_nrm[MOLN];
__device__ int   m_deg[MOLN];
__device__ int   m_cur[MOLN];
__device__ int   m_rowptr[MOLN + 1];
__device__ int   m_csr[MOLE];
__device__ int   m_bsum[128];
__device__ int   m_gptr[257];
__device__ float m_pool[256 * 312];
__device__ float m_fc1[256 * 1024];
__device__ float m_part[8 * 256 * 1024];
// shared tail
__device__ float g_cat[256 * 256];
__device__ float g_head[256 * 512];

static inline int gdiv(int n, int d) { return (n + d - 1) / d; }

// ---------------- small utility kernels ----------------
__global__ void k_zeroi(int* a, int n) {
    int i = blockIdx.x * blockDim.x + threadIdx.x;
    if (i < n) a[i] = 0;
}

__global__ void k_hist(const int* __restrict__ idx, int* __restrict__ acc, int n) {
    int i = blockIdx.x * blockDim.x + threadIdx.x;
    if (i < n) atomicAdd(&acc[idx[i]], 1);
}

// ---- multi-block exclusive scan ----
__global__ void k_scan_blk(const int* __restrict__ in, int* __restrict__ out,
                           int* __restrict__ bsum, int n) {
    __shared__ int wsum[32];
    int tid = threadIdx.x;
    int lane = tid & 31, wid = tid >> 5;
    int i = blockIdx.x * 1024 + tid;
    int v = (i < n) ? in[i] : 0;
    int s = v;
#pragma unroll
    for (int off = 1; off < 32; off <<= 1) {
        int t = __shfl_up_sync(0xffffffffu, s, off);
        if (lane >= off) s += t;
    }
    if (lane == 31) wsum[wid] = s;
    __syncthreads();
    if (wid == 0) {
        int ws = wsum[lane];
#pragma unroll
        for (int off = 1; off < 32; off <<= 1) {
            int t = __shfl_up_sync(0xffffffffu, ws, off);
            if (lane >= off) ws += t;
        }
        wsum[lane] = ws;
    }
    __syncthreads();
    int wofs = (wid > 0) ? wsum[wid - 1] : 0;
    int incl = wofs + s;
    if (i < n) out[i] = incl - v;
    if (tid == 1023) bsum[blockIdx.x] = incl;
}

__global__ void k_scan_small(int* __restrict__ b, int nb) {
    __shared__ int wsum[4];
    int tid = threadIdx.x;
    int lane = tid & 31, wid = tid >> 5;
    int v = (tid < nb) ? b[tid] : 0;
    int s = v;
#pragma unroll
    for (int off = 1; off < 32; off <<= 1) {
        int t = __shfl_up_sync(0xffffffffu, s, off);
        if (lane >= off) s += t;
    }
    if (lane == 31) wsum[wid] = s;
    __syncthreads();
    if (tid == 0) {
        int c = 0;
        for (int w = 0; w < 4; w++) { int t = wsum[w]; wsum[w] = c; c += t; }
    }
    __syncthreads();
    int excl = wsum[wid] + s - v;
    __syncthreads();
    if (tid < nb) b[tid] = excl;
    if (tid == nb - 1) b[nb] = excl + v;
}

// phase 3 fused: add block offsets, compute nrm, zero cur
__global__ void k_scan_add(int* __restrict__ out, const int* __restrict__ bsum,
                           const int* __restrict__ deg, float* __restrict__ nrm,
                           int* __restrict__ cur, int n, int nb) {
    int i = blockIdx.x * blockDim.x + threadIdx.x;
    if (i < n) {
        out[i] += bsum[i >> 10];
        nrm[i] = rsqrtf((float)deg[i] + 1.f);
        cur[i] = 0;
    }
    if (i == 0) out[n] = bsum[nb];
}

// fused per-graph histogram + exclusive scan (256 graphs), single block 1024
__global__ void k_ghist(const int* __restrict__ bat, int* __restrict__ gptr, int n) {
    __shared__ int bins[256];
    __shared__ int wsum[8];
    int tid = threadIdx.x;
    int lane = tid & 31, wid = tid >> 5;
    if (tid < 256) bins[tid] = 0;
    __syncthreads();
    for (int i = tid; i < n; i += 1024) atomicAdd(&bins[bat[i]], 1);
    __syncthreads();
    int v = (tid < 256) ? bins[tid] : 0;
    int s = v;
#pragma unroll
    for (int off = 1; off < 32; off <<= 1) {
        int t = __shfl_up_sync(0xffffffffu, s, off);
        if (lane >= off) s += t;
    }
    if (lane == 31 && wid < 8) wsum[wid] = s;
    __syncthreads();
    if (tid == 0) {
        int c = 0;
        for (int w = 0; w < 8; w++) { int t = wsum[w]; wsum[w] = c; c += t; }
    }
    __syncthreads();
    if (tid < 256) {
        int excl = wsum[wid] + s - v;
        gptr[tid] = excl;
        if (tid == 255) gptr[256] = excl + v;
    }
}

__global__ void k_fill(const int* __restrict__ src, const int* __restrict__ dst,
                       const int* __restrict__ rowptr, int* __restrict__ cur,
                       int* __restrict__ csr, int E) {
    int e = blockIdx.x * blockDim.x + threadIdx.x;
    if (e >= E) return;
    int d = dst[e];
    int p = rowptr[d] + atomicAdd(&cur[d], 1);
    csr[p] = src[e];
}

// ---------------- aggregation: y_i = nrm_i*(sum nrm_s x_s + nrm_i x_i) [+bias][relu]
template <int NF>
__global__ void k_agg(const float* __restrict__ x, const float* __restrict__ nrm,
                      const int* __restrict__ rowptr, const int* __restrict__ csr,
                      float* __restrict__ y, int N, int F,
                      const float* __restrict__ bias, int dorelu) {
    int warp = (blockIdx.x * blockDim.x + threadIdx.x) >> 5;
    int lane = threadIdx.x & 31;
    if (warp >= N) return;
    int beg = rowptr[warp], end = rowptr[warp + 1];
    float ni = nrm[warp];

    float acc[NF];
#pragma unroll
    for (int j = 0; j < NF; j++) acc[j] = 0.f;

    int e = beg;
    for (; e + 1 < end; e += 2) {
        int s0 = csr[e], s1 = csr[e + 1];
        float n0 = nrm[s0], n1 = nrm[s1];
        const float* x0 = x + (size_t)s0 * F;
        const float* x1 = x + (size_t)s1 * F;
#pragma unroll
        for (int j = 0; j < NF; j++) {
            int f = lane + 32 * j;
            if (f < F) acc[j] += x0[f] * n0 + x1[f] * n1;
        }
    }
    if (e < end) {
        int s0 = csr[e];
        float n0 = nrm[s0];
        const float* x0 = x + (size_t)s0 * F;
#pragma unroll
        for (int j = 0; j < NF; j++) {
            int f = lane + 32 * j;
            if (f < F) acc[j] += x0[f] * n0;
        }
    }
    const float* xi = x + (size_t)warp * F;
    float* yi = y + (size_t)warp * F;
#pragma unroll
    for (int j = 0; j < NF; j++) {
        int f = lane + 32 * j;
        if (f < F) {
            float v = ni * (acc[j] + ni * xi[f]);
            if (bias) v += bias[f];
            if (dorelu) v = fmaxf(v, 0.f);
            yi[f] = v;
        }
    }
}

// float2 variant (F % 2 == 0); F2 = F/2; 4-edge unroll
template <int NJ>
__global__ void k_agg2(const float2* __restrict__ x, const float* __restrict__ nrm,
                       const int* __restrict__ rowptr, const int* __restrict__ csr,
                       float2* __restrict__ y, int N, int F2,
                       const float2* __restrict__ bias, int dorelu) {
    int warp = (blockIdx.x * blockDim.x + threadIdx.x) >> 5;
    int lane = threadIdx.x & 31;
    if (warp >= N) return;
    int beg = rowptr[warp], end = rowptr[warp + 1];
    float ni = nrm[warp];

    float2 acc[NJ];
#pragma unroll
    for (int j = 0; j < NJ; j++) acc[j] = make_float2(0.f, 0.f);

    int e = beg;
    for (; e + 3 < end; e += 4) {
        int s0 = csr[e], s1 = csr[e + 1], s2 = csr[e + 2], s3 = csr[e + 3];
        float n0 = nrm[s0], n1 = nrm[s1], n2 = nrm[s2], n3 = nrm[s3];
        const float2* x0 = x + (size_t)s0 * F2;
        const float2* x1 = x + (size_t)s1 * F2;
        const float2* x2 = x + (size_t)s2 * F2;
        const float2* x3 = x + (size_t)s3 * F2;
#pragma unroll
        for (int j = 0; j < NJ; j++) {
            int f = lane + 32 * j;
            if (f < F2) {
                float2 v0 = x0[f], v1 = x1[f], v2 = x2[f], v3 = x3[f];
                acc[j].x += v0.x * n0 + v1.x * n1 + v2.x * n2 + v3.x * n3;
                acc[j].y += v0.y * n0 + v1.y * n1 + v2.y * n2 + v3.y * n3;
            }
        }
    }
    for (; e < end; e++) {
        int s0 = csr[e];
        float n0 = nrm[s0];
        const float2* x0 = x + (size_t)s0 * F2;
#pragma unroll
        for (int j = 0; j < NJ; j++) {
            int f = lane + 32 * j;
            if (f < F2) {
                float2 v0 = x0[f];
                acc[j].x += v0.x * n0;
                acc[j].y += v0.y * n0;
            }
        }
    }
    const float2* xi = x + (size_t)warp * F2;
    float2* yi = y + (size_t)warp * F2;
#pragma unroll
    for (int j = 0; j < NJ; j++) {
        int f = lane + 32 * j;
        if (f < F2) {
            float2 v = xi[f];
            float2 o;
            o.x = ni * (acc[j].x + ni * v.x);
            o.y = ni * (acc[j].y + ni * v.y);
            if (bias) { float2 b = bias[f]; o.x += b.x; o.y += b.y; }
            if (dorelu) { o.x = fmaxf(o.x, 0.f); o.y = fmaxf(o.y, 0.f); }
            yi[f] = o;
        }
    }
}

// float4 variant (F % 4 == 0); F4 = F/4; 4-edge unroll
template <int NJ>
__global__ void k_agg4(const float4* __restrict__ x, const float* __restrict__ nrm,
                       const int* __restrict__ rowptr, const int* __restrict__ csr,
                       float4* __restrict__ y, int N, int F4,
                       const float4* __restrict__ bias, int dorelu) {
    int warp = (blockIdx.x * blockDim.x + threadIdx.x) >> 5;
    int lane = threadIdx.x & 31;
    if (warp >= N) return;
    int beg = rowptr[warp], end = rowptr[warp + 1];
    float ni = nrm[warp];

    float4 acc[NJ];
#pragma unroll
    for (int j = 0; j < NJ; j++) acc[j] = make_float4(0.f, 0.f, 0.f, 0.f);

    int e = beg;
    for (; e + 3 < end; e += 4) {
        int s0 = csr[e], s1 = csr[e + 1], s2 = csr[e + 2], s3 = csr[e + 3];
        float n0 = nrm[s0], n1 = nrm[s1], n2 = nrm[s2], n3 = nrm[s3];
        const float4* x0 = x + (size_t)s0 * F4;
        const float4* x1 = x + (size_t)s1 * F4;
        const float4* x2 = x + (size_t)s2 * F4;
        const float4* x3 = x + (size_t)s3 * F4;
#pragma unroll
        for (int j = 0; j < NJ; j++) {
            int f = lane + 32 * j;
            if (f < F4) {
                float4 v0 = x0[f], v1 = x1[f], v2 = x2[f], v3 = x3[f];
                acc[j].x += v0.x * n0 + v1.x * n1 + v2.x * n2 + v3.x * n3;
                acc[j].y += v0.y * n0 + v1.y * n1 + v2.y * n2 + v3.y * n3;
                acc[j].z += v0.z * n0 + v1.z * n1 + v2.z * n2 + v3.z * n3;
                acc[j].w += v0.w * n0 + v1.w * n1 + v2.w * n2 + v3.w * n3;
            }
        }
    }
    for (; e < end; e++) {
        int s0 = csr[e];
        float n0 = nrm[s0];
        const float4* x0 = x + (size_t)s0 * F4;
#pragma unroll
        for (int j = 0; j < NJ; j++) {
            int f = lane + 32 * j;
            if (f < F4) {
                float4 v0 = x0[f];
                acc[j].x += v0.x * n0;
                acc[j].y += v0.y * n0;
                acc[j].z += v0.z * n0;
                acc[j].w += v0.w * n0;
            }
        }
    }
    const float4* xi = x + (size_t)warp * F4;
    float4* yi = y + (size_t)warp * F4;
#pragma unroll
    for (int j = 0; j < NJ; j++) {
        int f = lane + 32 * j;
        if (f < F4) {
            float4 v = xi[f];
            float4 o;
            o.x = ni * (acc[j].x + ni * v.x);
            o.y = ni * (acc[j].y + ni * v.y);
            o.z = ni * (acc[j].z + ni * v.z);
            o.w = ni * (acc[j].w + ni * v.w);
            if (bias) {
                float4 b = bias[f];
                o.x += b.x; o.y += b.y; o.z += b.z; o.w += b.w;
            }
            if (dorelu) {
                o.x = fmaxf(o.x, 0.f); o.y = fmaxf(o.y, 0.f);
                o.z = fmaxf(o.z, 0.f); o.w = fmaxf(o.w, 0.f);
            }
            yi[f] = o;
        }
    }
}

static void launch_agg(const float* x, const float* nrm, const int* rp, const int* csr,
                       float* y, int N, int F, const float* bias, int dorelu,
                       cudaStream_t st) {
    int blocks = gdiv(N, 8);
    if ((F & 3) == 0) {
        int F4 = F >> 2;
        int nj = gdiv(F4, 32);
        if (nj == 1)      k_agg4<1><<<blocks, 256, 0, st>>>((const float4*)x, nrm, rp, csr, (float4*)y, N, F4, (const float4*)bias, dorelu);
        else if (nj == 2) k_agg4<2><<<blocks, 256, 0, st>>>((const float4*)x, nrm, rp, csr, (float4*)y, N, F4, (const float4*)bias, dorelu);
        else              k_agg4<3><<<blocks, 256, 0, st>>>((const float4*)x, nrm, rp, csr, (float4*)y, N, F4, (const float4*)bias, dorelu);
        return;
    }
    if ((F & 1) == 0) {
        int F2 = F >> 1;
        int nj = gdiv(F2, 32);
        if (nj == 1)      k_agg2<1><<<blocks, 256, 0, st>>>((const float2*)x, nrm, rp, csr, (float2*)y, N, F2, (const float2*)bias, dorelu);
        else if (nj == 2) k_agg2<2><<<blocks, 256, 0, st>>>((const float2*)x, nrm, rp, csr, (float2*)y, N, F2, (const float2*)bias, dorelu);
        else              k_agg2<3><<<blocks, 256, 0, st>>>((const float2*)x, nrm, rp, csr, (float2*)y, N, F2, (const float2*)bias, dorelu);
        return;
    }
    int nf = gdiv(F, 32);
    switch (nf) {
        case 2: k_agg<2><<<blocks, 256, 0, st>>>(x, nrm, rp, csr, y, N, F, bias, dorelu); break;
        case 3: k_agg<3><<<blocks, 256, 0, st>>>(x, nrm, rp, csr, y, N, F, bias, dorelu); break;
        case 4: k_agg<4><<<blocks, 256, 0, st>>>(x, nrm, rp, csr, y, N, F, bias, dorelu); break;
        case 5: k_agg<5><<<blocks, 256, 0, st>>>(x, nrm, rp, csr, y, N, F, bias, dorelu); break;
        default: k_agg<8><<<blocks, 256, 0, st>>>(x, nrm, rp, csr, y, N, F, bias, dorelu); break;
    }
}

// ---------------- mean pool over contiguous per-graph ranges ----------------
__global__ void k_pool(const float* __restrict__ x, const int* __restrict__ gptr,
                       float* __restrict__ pool, int F) {
    int g = blockIdx.x;
    int beg = gptr[g], end = gptr[g + 1];
    float inv = 1.f / fmaxf((float)(end - beg), 1.f);
    for (int f = threadIdx.x; f < F; f += blockDim.x) {
        float s0 = 0.f, s1 = 0.f, s2 = 0.f, s3 = 0.f;
        int i = beg;
        for (; i + 3 < end; i += 4) {
            s0 += x[(size_t)(i + 0) * F + f];
            s1 += x[(size_t)(i + 1) * F + f];
            s2 += x[(size_t)(i + 2) * F + f];
            s3 += x[(size_t)(i + 3) * F + f];
        }
        for (; i < end; i++) s0 += x[(size_t)i * F + f];
        pool[(size_t)g * F + f] = (s0 + s1 + s2 + s3) * inv;
    }
}

// ---------------- SIMT SGEMM (templated tiles, double-buffered, LDS.128 frags) ---
template <int MH, int NH>
__global__ __launch_bounds__(256) void k_sgemm(
    const float* __restrict__ A, const float* __restrict__ W,
    const float* __restrict__ bias, float* __restrict__ C,
    int N, int K, int M, int ldc, int relu)
{
    constexpr int TBM = 64 * MH;
    constexpr int TBN = 64 * NH;
    constexpr int CA = TBM / 32;
    constexpr int TPRA = 8 / CA;
    constexpr int CB = TBN / 32;

    __shared__ __align__(16) float As[2][8][TBM];
    __shared__ __align__(16) float Bs[2][8][TBN];

    int tid = threadIdx.x;
    int row0 = blockIdx.y * TBM;
    int col0 = blockIdx.x * TBN;
    int tx = tid & 15;
    int ty = tid >> 4;

    int a_r = tid / TPRA;
    int a_k = (tid % TPRA) * CA;
    int b_k = tid >> 5;
    int b_c = (tid & 31) * CB;

    int ar = row0 + a_r;
    const float* Arow = A + (size_t)(ar < N ? ar : 0) * K;
    bool a_ok = (ar < N);

    float acc[4 * MH][4 * NH];
#pragma unroll
    for (int i = 0; i < 4 * MH; i++)
#pragma unroll
        for (int j = 0; j < 4 * NH; j++) acc[i][j] = 0.f;

    float ra[CA], rb[CB];
    int kt = (K + 7) / 8;

#pragma unroll
    for (int i = 0; i < CA; i++) {
        int kc = a_k + i;
        ra[i] = (a_ok && kc < K) ? Arow[kc] : 0.f;
    }
#pragma unroll
    for (int i = 0; i < CB; i++) {
        int bc = col0 + b_c + i;
        rb[i] = (b_k < K && bc < M) ? W[(size_t)b_k * M + bc] : 0.f;
    }
#pragma unroll
    for (int i = 0; i < CA; i++) As[0][a_k + i][a_r] = ra[i];
#pragma unroll
    for (int i = 0; i < CB; i++) Bs[0][b_k][b_c + i] = rb[i];
    __syncthreads();

    int buf = 0;
    for (int t = 0; t < kt; t++) {
        int k_next = (t + 1) * 8;
        if (t + 1 < kt) {
#pragma unroll
            for (int i = 0; i < CA; i++) {
                int kc = k_next + a_k + i;
                ra[i] = (a_ok && kc < K) ? Arow[kc] : 0.f;
            }
            int bk = k_next + b_k;
#pragma unroll
            for (int i = 0; i < CB; i++) {
                int bc = col0 + b_c + i;
                rb[i] = (bk < K && bc < M) ? W[(size_t)bk * M + bc] : 0.f;
            }
        }

#pragma unroll
        for (int kk = 0; kk < 8; kk++) {
            float4 af4[MH], bf4[NH];
#pragma unroll
            for (int h = 0; h < MH; h++)
                af4[h] = *reinterpret_cast<const float4*>(&As[buf][kk][h * 64 + ty * 4]);
#pragma unroll
            for (int h = 0; h < NH; h++)
                bf4[h] = *reinterpret_cast<const float4*>(&Bs[buf][kk][h * 64 + tx * 4]);
            float af[4 * MH], bf[4 * NH];
#pragma unroll
            for (int h = 0; h < MH; h++) {
                af[h * 4 + 0] = af4[h].x; af[h * 4 + 1] = af4[h].y;
                af[h * 4 + 2] = af4[h].z; af[h * 4 + 3] = af4[h].w;
            }
#pragma unroll
            for (int h = 0; h < NH; h++) {
                bf[h * 4 + 0] = bf4[h].x; bf[h * 4 + 1] = bf4[h].y;
                bf[h * 4 + 2] = bf4[h].z; bf[h * 4 + 3] = bf4[h].w;
            }
#pragma unroll
            for (int i = 0; i < 4 * MH; i++)
#pragma unroll
                for (int j = 0; j < 4 * NH; j++) acc[i][j] += af[i] * bf[j];
        }

        if (t + 1 < kt) {
            int nb = buf ^ 1;
#pragma unroll
            for (int i = 0; i < CA; i++) As[nb][a_k + i][a_r] = ra[i];
#pragma unroll
            for (int i = 0; i < CB; i++) Bs[nb][b_k][b_c + i] = rb[i];
            __syncthreads();
            buf = nb;
        }
    }

#pragma unroll
    for (int hm = 0; hm < MH; hm++) {
#pragma unroll
        for (int i = 0; i < 4; i++) {
            int r = row0 + hm * 64 + ty * 4 + i;
            if (r >= N) continue;
#pragma unroll
            for (int hn = 0; hn < NH; hn++) {
#pragma unroll
                for (int j = 0; j < 4; j++) {
                    int c = col0 + hn * 64 + tx * 4 + j;
                    if (c >= M) continue;
                    float v = acc[hm * 4 + i][hn * 4 + j] + (bias ? bias[c] : 0.f);
                    if (relu) v = fmaxf(v, 0.f);
                    C[(size_t)r * ldc + c] = v;
                }
            }
        }
    }
}

// ---------------- split-K SGEMM: 64x64 tile, grid.z = K-chunks, writes partials ----
__global__ __launch_bounds__(256) void k_sgemm_sk(
    const float* __restrict__ A, const float* __restrict__ W,
    float* __restrict__ part, int N, int K, int M, int Kc)
{
    __shared__ __align__(16) float As[2][8][64];
    __shared__ __align__(16) float Bs[2][8][64];

    int tid = threadIdx.x;
    int row0 = blockIdx.y * 64;
    int col0 = blockIdx.x * 64;
    int z = blockIdx.z;
    int k0 = z * Kc;
    int kEff = K - k0; if (kEff > Kc) kEff = Kc;
    int tx = tid & 15;
    int ty = tid >> 4;

    int a_r = tid >> 2;
    int a_k = (tid & 3) * 2;
    int b_k = tid >> 5;
    int b_c = (tid & 31) * 2;

    int ar = row0 + a_r;
    const float* Arow = A + (size_t)(ar < N ? ar : 0) * K + k0;
    bool a_ok = (ar < N);

    float acc[4][4];
#pragma unroll
    for (int i = 0; i < 4; i++)
#pragma unroll
        for (int j = 0; j < 4; j++) acc[i][j] = 0.f;

    float ra[2], rb[2];
    int kt = (kEff + 7) / 8;

#pragma unroll
    for (int i = 0; i < 2; i++) {
        int kc = a_k + i;
        ra[i] = (a_ok && kc < kEff) ? Arow[kc] : 0.f;
    }
#pragma unroll
    for (int i = 0; i < 2; i++) {
        int bc = col0 + b_c + i;
        rb[i] = (b_k < kEff && bc < M) ? W[(size_t)(k0 + b_k) * M + bc] : 0.f;
    }
#pragma unroll
    for (int i = 0; i < 2; i++) As[0][a_k + i][a_r] = ra[i];
#pragma unroll
    for (int i = 0; i < 2; i++) Bs[0][b_k][b_c + i] = rb[i];
    __syncthreads();

    int buf = 0;
    for (int t = 0; t < kt; t++) {
        int k_next = (t + 1) * 8;
        if (t + 1 < kt) {
#pragma unroll
            for (int i = 0; i < 2; i++) {
                int kc = k_next + a_k + i;
                ra[i] = (a_ok && kc < kEff) ? Arow[kc] : 0.f;
            }
            int bk = k_next + b_k;
#pragma unroll
            for (int i = 0; i < 2; i++) {
                int bc = col0 + b_c + i;
                rb[i] = (bk < kEff && bc < M) ? W[(size_t)(k0 + bk) * M + bc] : 0.f;
            }
        }

#pragma unroll
        for (int kk = 0; kk < 8; kk++) {
            float4 a4 = *reinterpret_cast<const float4*>(&As[buf][kk][ty * 4]);
            float4 b4 = *reinterpret_cast<const float4*>(&Bs[buf][kk][tx * 4]);
            float af[4] = {a4.x, a4.y, a4.z, a4.w};
            float bf[4] = {b4.x, b4.y, b4.z, b4.w};
#pragma unroll
            for (int i = 0; i < 4; i++)
#pragma unroll
                for (int j = 0; j < 4; j++) acc[i][j] += af[i] * bf[j];
        }

        if (t + 1 < kt) {
            int nb = buf ^ 1;
#pragma unroll
            for (int i = 0; i < 2; i++) As[nb][a_k + i][a_r] = ra[i];
#pragma unroll
            for (int i = 0; i < 2; i++) Bs[nb][b_k][b_c + i] = rb[i];
            __syncthreads();
            buf = nb;
        }
    }

    float* P = part + (size_t)z * N * M;
#pragma unroll
    for (int i = 0; i < 4; i++) {
        int r = row0 + ty * 4 + i;
        if (r >= N) continue;
#pragma unroll
        for (int j = 0; j < 4; j++) {
            int c = col0 + tx * 4 + j;
            if (c >= M) continue;
            P[(size_t)r * M + c] = acc[i][j];
        }
    }
}

// deterministic fixed-order reduce of KS partials, + bias/relu
__global__ void k_red(const float* __restrict__ part, const float* __restrict__ bias,
                      float* __restrict__ C, int N, int M, int ldc, int relu, int KS) {
    int i = blockIdx.x * blockDim.x + threadIdx.x;
    if (i >= N * M) return;
    float s = 0.f;
    for (int z = 0; z < KS; z++) s += part[(size_t)z * N * M + i];
    int r = i / M, c = i - r * M;
    float v = s + (bias ? bias[c] : 0.f);
    if (relu) v = fmaxf(v, 0.f);
    C[(size_t)r * ldc + c] = v;
}

static void launch_sgemm(const float* A, const float* W, const float* bias, float* C,
                         int N, int K, int M, int ldc, int relu, cudaStream_t st,
                         float* part = nullptr) {
    if (part && N <= 256 && K >= 192) {
        int KS = 8;
        int Kc = gdiv(K, KS);
        Kc = (Kc + 7) & ~7;
        KS = gdiv(K, Kc);
        dim3 grid(gdiv(M, 64), gdiv(N, 64), KS);
        k_sgemm_sk<<<grid, 256, 0, st>>>(A, W, part, N, K, M, Kc);
        k_red<<<gdiv(N * M, 256), 256, 0, st>>>(part, bias, C, N, M, ldc, relu, KS);
        return;
    }
    int best_bm = 128, best_bn = 128;
    double best_score = 1e30;
    for (int bm = 128; bm >= 64; bm -= 64) {
        for (int bn = 128; bn >= 64; bn -= 64) {
            double padw = (double)((long)gdiv(N, bm) * bm) * ((long)gdiv(M, bn) * bn);
            long ctas = (long)gdiv(N, bm) * gdiv(M, bn);
            double occ_pen = (ctas < 296) ? (296.0 / (double)ctas) : 1.0;
            double tile_pen = (bm == 64 ? 1.06 : 1.0) * (bn == 64 ? 1.06 : 1.0);
            double score = padw * occ_pen * tile_pen;
            if (score < best_score) { best_score = score; best_bm = bm; best_bn = bn; }
        }
    }
    dim3 grid(gdiv(M, best_bn), gdiv(N, best_bm));
    if (best_bm == 128 && best_bn == 128)      k_sgemm<2, 2><<<grid, 256, 0, st>>>(A, W, bias, C, N, K, M, ldc, relu);
    else if (best_bm == 128 && best_bn == 64)  k_sgemm<2, 1><<<grid, 256, 0, st>>>(A, W, bias, C, N, K, M, ldc, relu);
    else if (best_bm == 64 && best_bn == 128)  k_sgemm<1, 2><<<grid, 256, 0, st>>>(A, W, bias, C, N, K, M, ldc, relu);
    else                                       k_sgemm<1, 1><<<grid, 256, 0, st>>>(A, W, bias, C, N, K, M, ldc, relu);
}

// ---------------- branch orchestration ----------------
static void run_branch(const float* x0, const int* ei, int E, const int* bat, int N,
                       int F0, int F1, int F2, int F3,
                       const float* w1, const float* b1,
                       const float* w2, const float* b2,
                       const float* w3, const float* b3,
                       const float* fw1, const float* fb1,
                       const float* fw2, const float* fb2,
                       float* cat_ptr,
                       float* Y, float* A, float* Bf,
                       float* nrm, int* deg, int* cur, int* rowptr, int* csr,
                       int* bsum, int* gptr, float* pool, float* fc1, float* part,
                       cudaStream_t st)
{
    const int* src = ei;
    const int* dst = ei + E;
    const int T = 256;
    int nb = gdiv(N, 1024);

    k_zeroi<<<gdiv(N, T), T, 0, st>>>(deg, N);
    k_hist<<<gdiv(E, T), T, 0, st>>>(dst, deg, E);
    k_scan_blk<<<nb, 1024, 0, st>>>(deg, rowptr, bsum, N);
    launch_sgemm(x0, w1, nullptr, Y, N, F0, F1, F1, 0, st);
    k_scan_small<<<1, 128, 0, st>>>(bsum, nb);
    k_scan_add<<<gdiv(N, T), T, 0, st>>>(rowptr, bsum, deg, nrm, cur, N, nb);
    k_fill<<<gdiv(E, T), T, 0, st>>>(src, dst, rowptr, cur, csr, E);

    // layer 1 epilogue: A = relu(nrm*(agg(Y) + nrm*Y) + b1)
    launch_agg(Y, nrm, rowptr, csr, A, N, F1, b1, 1, st);

    // layer 2
    launch_agg(A, nrm, rowptr, csr, Y, N, F1, nullptr, 0, st);
    launch_sgemm(Y, w2, b2, Bf, N, F1, F2, F2, 1, st);

    // layer 3
    launch_agg(Bf, nrm, rowptr, csr, Y, N, F2, nullptr, 0, st);
    launch_sgemm(Y, w3, b3, A, N, F2, F3, F3, 1, st);

    // mean pool (batch sorted -> contiguous ranges)
    k_ghist<<<1, 1024, 0, st>>>(bat, gptr, N);
    k_pool<<<256, 256, 0, st>>>(A, gptr, pool, F3);

    // fc1 (split-K, relu), fc2 (split-K) -> concat slice (ldc=256)
    launch_sgemm(pool, fw1, fb1, fc1, 256, F3, 1024, 1024, 1, st, part);
    launch_sgemm(fc1, fw2, fb2, cat_ptr, 256, 1024, 128, 256, 0, st, part);
}

extern "C" void kernel_launch(void* const* d_in, const int* in_sizes, int n_in,
                              void* d_out, int out_size)
{
    static cudaStream_t s2 = nullptr;
    static cudaEvent_t evFork = nullptr, evJoin = nullptr;
    if (!s2) {
        cudaStreamCreateWithFlags(&s2, cudaStreamNonBlocking);
        cudaEventCreateWithFlags(&evFork, cudaEventDisableTiming);
        cudaEventCreateWithFlags(&evJoin, cudaEventDisableTiming);
    }

    float *Y, *A, *Bf, *nrm, *pool, *fc1, *part;
    int *deg, *cur, *rowptr, *csr, *bsum, *gptr;
    float *mY, *mA, *mBf, *mnrm, *mpool, *mfc1, *mpart;
    int *mdeg, *mcur, *mrowptr, *mcsr, *mbsum, *mgptr;
    float *cat, *head;
    cudaGetSymbolAddress((void**)&Y,       g_Y);
    cudaGetSymbolAddress((void**)&A,       g_A);
    cudaGetSymbolAddress((void**)&Bf,      g_B);
    cudaGetSymbolAddress((void**)&nrm,     g_nrm);
    cudaGetSymbolAddress((void**)&deg,     g_deg);
    cudaGetSymbolAddress((void**)&cur,     g_cur);
    cudaGetSymbolAddress((void**)&rowptr,  g_rowptr);
    cudaGetSymbolAddress((void**)&csr,     g_csr);
    cudaGetSymbolAddress((void**)&bsum,    g_bsum);
    cudaGetSymbolAddress((void**)&gptr,    g_gptr);
    cudaGetSymbolAddress((void**)&pool,    g_pool);
    cudaGetSymbolAddress((void**)&fc1,     g_fc1);
    cudaGetSymbolAddress((void**)&part,    g_part);
    cudaGetSymbolAddress((void**)&mY,      m_Y);
    cudaGetSymbolAddress((void**)&mA,      m_A);
    cudaGetSymbolAddress((void**)&mBf,     m_B);
    cudaGetSymbolAddress((void**)&mnrm,    m_nrm);
    cudaGetSymbolAddress((void**)&mdeg,    m_deg);
    cudaGetSymbolAddress((void**)&mcur,    m_cur);
    cudaGetSymbolAddress((void**)&mrowptr, m_rowptr);
    cudaGetSymbolAddress((void**)&mcsr,    m_csr);
    cudaGetSymbolAddress((void**)&mbsum,   m_bsum);
    cudaGetSymbolAddress((void**)&mgptr,   m_gptr);
    cudaGetSymbolAddress((void**)&mpool,   m_pool);
    cudaGetSymbolAddress((void**)&mfc1,    m_fc1);
    cudaGetSymbolAddress((void**)&mpart,   m_part);
    cudaGetSymbolAddress((void**)&cat,     g_cat);
    cudaGetSymbolAddress((void**)&head,    g_head);

    const float* mol_x  = (const float*)d_in[0];
    const int*   mol_ei = (const int*)  d_in[1];
    const int*   mol_b  = (const int*)  d_in[2];
    const float* pro_x  = (const float*)d_in[3];
    const int*   pro_ei = (const int*)  d_in[4];
    const int*   pro_b  = (const int*)  d_in[5];

    int N_mol = in_sizes[2];
    int E_mol = in_sizes[1] / 2;
    int F_mol = in_sizes[0] / N_mol;     // 78
    int N_pro = in_sizes[5];
    int E_pro = in_sizes[4] / 2;
    int F_pro = in_sizes[3] / N_pro;     // 54

    const float* mw1  = (const float*)d_in[6];
    const float* mb1  = (const float*)d_in[7];
    const float* mw2  = (const float*)d_in[8];
    const float* mb2  = (const float*)d_in[9];
    const float* mw3  = (const float*)d_in[10];
    const float* mb3  = (const float*)d_in[11];
    const float* mfw1 = (const float*)d_in[12];
    const float* mfb1 = (const float*)d_in[13];
    const float* mfw2 = (const float*)d_in[14];
    const float* mfb2 = (const float*)d_in[15];
    const float* pw1  = (const float*)d_in[16];
    const float* pb1  = (const float*)d_in[17];
    const float* pw2  = (const float*)d_in[18];
    const float* pb2  = (const float*)d_in[19];
    const float* pw3  = (const float*)d_in[20];
    const float* pb3  = (const float*)d_in[21];
    const float* pfw1 = (const float*)d_in[22];
    const float* pfb1 = (const float*)d_in[23];
    const float* pfw2 = (const float*)d_in[24];
    const float* pfb2 = (const float*)d_in[25];
    const float* fc1w = (const float*)d_in[26];
    const float* fc1b = (const float*)d_in[27];
    const float* fc2w = (const float*)d_in[28];
    const float* fc2b = (const float*)d_in[29];
    const float* outw = (const float*)d_in[30];
    const float* outb = (const float*)d_in[31];

    // fork: mol branch on s2, pro branch on legacy stream
    cudaEventRecord(evFork, 0);
    cudaStreamWaitEvent(s2, evFork, 0);

    run_branch(mol_x, mol_ei, E_mol, mol_b, N_mol,
               F_mol, F_mol, 2 * F_mol, 4 * F_mol,
               mw1, mb1, mw2, mb2, mw3, mb3,
               mfw1, mfb1, mfw2, mfb2,
               cat,
               mY, mA, mBf, mnrm, mdeg, mcur, mrowptr, mcsr,
               mbsum, mgptr, mpool, mfc1, mpart, s2);

    run_branch(pro_x, pro_ei, E_pro, pro_b, N_pro,
               F_pro, F_pro, 2 * F_pro, 4 * F_pro,
               pw1, pb1, pw2, pb2, pw3, pb3,
               pfw1, pfb1, pfw2, pfb2,
               cat + 128,
               Y, A, Bf, nrm, deg, cur, rowptr, csr,
               bsum, gptr, pool, fc1, part, 0);

    // join: head waits for mol branch
    cudaEventRecord(evJoin, s2);
    cudaStreamWaitEvent(0, evJoin, 0);

    // combined head (all split-K where K >= 192)
    launch_sgemm(cat,  fc1w, fc1b, fc1,           256, 256,  1024, 1024, 1, 0, part);
    launch_sgemm(fc1,  fc2w, fc2b, head,          256, 1024, 512,  512,  1, 0, part);
    launch_sgemm(head, outw, outb, (float*)d_out, 256, 512,  1,    1,    0, 0, part);
}